// round 14
// baseline (speedup 1.0000x reference)
#include <cuda_runtime.h>
#include <math.h>

#define NMAX 20000
#define NPAD 21120                 /* NPARTK * chunk (15 * 11 * 128) */
#define KNN 6
#define KCAND 6
#define NPARTK 15
#define NSUB 4
#define CTOT (NPARTK*NSUB*KCAND)   /* 360 candidate slots per node */
#define CSLICE (CTOT/8)            /* 45 per refine thread */
#define CMERGE 48                  /* 8 slices x 6 */

typedef unsigned int u32;

// ---------------- scratch (device globals; no allocation allowed) ----------------
__device__ __align__(16) float g_cnt [NMAX];
__device__ __align__(16) float g_agg1[NMAX*16];
__device__ __align__(16) float g_x1  [NMAX*16];
__device__ __align__(16) float g_x1t [NPAD*16];   /* zero-init pad rows never written */
__device__ __align__(16) float g_sq1 [NPAD];
__device__ __align__(16) float g_y1  [NMAX*32];
__device__ __align__(16) float g_y1t [NPAD*32];
__device__ __align__(16) float g_sq2 [NPAD];
__device__ __align__(16) float g_cat0[NMAX*48];
__device__ __align__(16) float g_agg2[NMAX*48];
__device__ __align__(16) float g_x3  [NMAX*64];
__device__ __align__(16) float g_y2  [NMAX*32];
__device__ __align__(16) float g_h1  [NMAX*96];
__device__ __align__(16) int   g_ci  [NMAX*CTOT];
__device__ __align__(16) float g_md  [NMAX*CMERGE];
__device__ __align__(16) int   g_mi  [NMAX*CMERGE];

#define MMA_TF32(c0,c1,c2,c3,a0,a1,a2,a3,b0,b1) \
    asm volatile("mma.sync.aligned.m16n8k8.row.col.f32.tf32.tf32.f32 " \
        "{%0,%1,%2,%3}, {%4,%5,%6,%7}, {%8,%9}, {%0,%1,%2,%3};" \
        : "+f"(c0), "+f"(c1), "+f"(c2), "+f"(c3) \
        : "r"(a0), "r"(a1), "r"(a2), "r"(a3), "r"(b0), "r"(b1))

// cp.async helpers (LDGSTS)
__device__ __forceinline__ void cpa16(u32 dst, const void* src){
    asm volatile("cp.async.cg.shared.global [%0], [%1], 16;" :: "r"(dst), "l"(src));
}
#define CPA_COMMIT() asm volatile("cp.async.commit_group;")
#define CPA_WAIT1()  asm volatile("cp.async.wait_group 1;")
#define CPA_WAIT0()  asm volatile("cp.async.wait_group 0;")

// float key: distance mantissa truncated to high 17 bits, j spliced into low 15.
__device__ __forceinline__ float fpack(float e, u32 j){
    return __uint_as_float((__float_as_uint(e) & 0xFFFF8000u) | j);
}
#define KEY_INIT __uint_as_float(0x7F7FFFFFu)

#define CMPX(a,b) { float _lo = fminf(a,b); b = fmaxf(a,b); a = _lo; }

// Batcher odd-even mergesort network for 8 (19 comparators)
__device__ __forceinline__ void sort8(float s[8]){
    CMPX(s[0],s[1]); CMPX(s[2],s[3]); CMPX(s[4],s[5]); CMPX(s[6],s[7]);
    CMPX(s[0],s[2]); CMPX(s[1],s[3]); CMPX(s[4],s[6]); CMPX(s[5],s[7]);
    CMPX(s[1],s[2]); CMPX(s[5],s[6]);
    CMPX(s[0],s[4]); CMPX(s[1],s[5]); CMPX(s[2],s[6]); CMPX(s[3],s[7]);
    CMPX(s[2],s[4]); CMPX(s[3],s[5]);
    CMPX(s[1],s[2]); CMPX(s[3],s[4]); CMPX(s[5],s[6]);
}

// merge sorted L[6] with sorted s[8], keep lowest 6 sorted (bitonic halver).
__device__ __forceinline__ void merge86(float L[KCAND], const float s[8]){
    float t0 = fminf(L[0], s[5]);
    float t1 = fminf(L[1], s[4]);
    float t2 = fminf(L[2], s[3]);
    float t3 = fminf(L[3], s[2]);
    float t4 = fminf(L[4], s[1]);
    float t5 = fminf(L[5], s[0]);
    CMPX(t0,t3); CMPX(t1,t4); CMPX(t2,t5);
    CMPX(t0,t1); CMPX(t1,t2); CMPX(t0,t1);
    CMPX(t3,t4); CMPX(t4,t5); CMPX(t3,t4);
    L[0]=t0; L[1]=t1; L[2]=t2; L[3]=t3; L[4]=t4; L[5]=t5;
}

// ---------------- init: agg1 = x (self loop), cnt = 1, sq pads = 1e30 ----------------
__global__ void init1_kernel(const float* __restrict__ x, int n, int npad){
    int t = blockIdx.x*blockDim.x + threadIdx.x;
    if (t < n*16) g_agg1[t] = x[t];
    if (t < n)    g_cnt[t]  = 1.0f;
    if (t >= n && t < npad){ g_sq1[t] = 1e30f; g_sq2[t] = 1e30f; }
}

// ---------------- scatter-add of x[src] into agg1[dst], count edges ----------------
__global__ void scatter1_kernel(const int* __restrict__ src, const int* __restrict__ dst,
                                const float* __restrict__ x, int E){
    int t = blockIdx.x*blockDim.x + threadIdx.x;
    int e = t >> 2;
    if (e >= E) return;
    int q = t & 3;
    int s = src[e], d = dst[e];
    if (q == 0) atomicAdd(&g_cnt[d], 1.0f);
    float4 v = reinterpret_cast<const float4*>(x)[s*4 + q];
    float* a = &g_agg1[d*16 + q*4];
    atomicAdd(a+0, v.x); atomicAdd(a+1, v.y); atomicAdd(a+2, v.z); atomicAdd(a+3, v.w);
}

// ---------------- feast: out = relu((agg/cnt) @ W + b); optional sq/cat0/transpose folds --------
template<int IN, int OUT, bool WSQ, bool CAT, bool TR>
__global__ void feast_kernel(const float* __restrict__ agg, const float* __restrict__ W,
                             const float* __restrict__ b, int n,
                             float* __restrict__ out, float* __restrict__ sqout,
                             float* __restrict__ tout){
    __shared__ float sW[IN*OUT];
    __shared__ float sb[OUT];
    for (int t = threadIdx.x; t < IN*OUT; t += blockDim.x) sW[t] = W[t];
    for (int t = threadIdx.x; t < OUT;    t += blockDim.x) sb[t] = b[t];
    __syncthreads();
    int i = blockIdx.x*blockDim.x + threadIdx.x;
    if (i >= n) return;
    float inv = 1.0f / g_cnt[i];
    float acc[OUT];
#pragma unroll
    for (int c = 0; c < OUT; c++) acc[c] = sb[c];
    for (int d = 0; d < IN; d++){
        float v = agg[i*IN+d] * inv;
#pragma unroll
        for (int c = 0; c < OUT; c++) acc[c] = fmaf(v, sW[d*OUT+c], acc[c]);
    }
    float sq = 0.f;
#pragma unroll
    for (int c = 0; c < OUT; c++){
        float r = fmaxf(acc[c], 0.f);
        out[i*OUT+c] = r;
        if (CAT){ g_cat0[i*48+c] = r; g_agg2[i*48+c] = r; }
        if (TR) tout[i*OUT + (c&3)*(OUT/4) + (c>>2)] = r;
        sq = fmaf(r, r, sq);
    }
    if (WSQ) sqout[i] = sq;
}

// ---------------- tensor-core kNN: cp.async double-buffered, tf32 MMA, sorted selection --------
template<int DIM, int PAD>
__global__ void __launch_bounds__(256,4)
knn_mma_kernel(const float* __restrict__ Xt, const float* __restrict__ sq,
               int n, int chunk){
    const int KC = DIM/8;
    const int Q4 = DIM/4;
    __shared__ float bs[2][128*PAD];
    __shared__ float sqs[2][128];

    int tid = threadIdx.x;
    int w = tid >> 5;
    int lane = tid & 31;
    int g = lane & 3;
    int rsub = lane >> 2;
    int qbase = blockIdx.x*128 + w*16;
    int r0 = qbase + rsub;
    int r1 = r0 + 8;
    int p = blockIdx.y;
    int jbeg = p * chunk;
    int T = chunk >> 7;

    int rr0 = min(r0, n-1), rr1 = min(r1, n-1);
    u32 a0[KC], a1[KC], a2[KC], a3[KC];
    {
        const float2* xa = (const float2*)(Xt + (size_t)rr0*DIM) + g*(Q4/2);
        const float2* xb = (const float2*)(Xt + (size_t)rr1*DIM) + g*(Q4/2);
#pragma unroll
        for (int kc = 0; kc < KC; kc++){
            float2 va = xa[kc], vb = xb[kc];
            a0[kc] = __float_as_uint(-2.0f * va.x);
            a2[kc] = __float_as_uint(-2.0f * va.y);
            a1[kc] = __float_as_uint(-2.0f * vb.x);
            a3[kc] = __float_as_uint(-2.0f * vb.y);
        }
    }

    u32 sb0 = (u32)__cvta_generic_to_shared(&bs[0][0]);
    u32 sb1 = (u32)__cvta_generic_to_shared(&bs[1][0]);
    u32 sq0 = (u32)__cvta_generic_to_shared(&sqs[0][0]);
    u32 sq1 = (u32)__cvta_generic_to_shared(&sqs[1][0]);

    float LA[KCAND], LB[KCAND];
#pragma unroll
    for (int k = 0; k < KCAND; k++){ LA[k] = KEY_INIT; LB[k] = KEY_INIT; }

    #define STAGE(BUF, JT) { \
        u32 _bb = (BUF) ? sb1 : sb0; \
        u32 _bq = (BUF) ? sq1 : sq0; \
        _Pragma("unroll") \
        for (int idx = tid; idx < 128*Q4; idx += 256){ \
            int jr = idx / Q4, q = idx - jr*Q4; \
            cpa16(_bb + (u32)(jr*PAD + q*4)*4u, Xt + (size_t)((JT)+jr)*DIM + q*4); \
        } \
        if (tid < 32) cpa16(_bq + tid*16u, sq + (JT) + tid*4); \
    }

    STAGE(0, jbeg);
    CPA_COMMIT();

    for (int t = 0; t < T; t++){
        int cur = t & 1;
        if (t + 1 < T){
            STAGE(1-cur, jbeg + (t+1)*128);
            CPA_COMMIT();
            CPA_WAIT1();
        } else {
            CPA_WAIT0();
        }
        __syncthreads();

        const float* bsc = &bs[cur][0];
        const float* sqc = &sqs[cur][0];
        int jt = jbeg + t*128;

#pragma unroll
        for (int jg = 0; jg < 128; jg += 32){
            float SA[8], SB[8];
#pragma unroll
            for (int st = 0; st < 4; st++){
                int js = jg + st*8;
                float2 s2 = *reinterpret_cast<const float2*>(&sqc[js + 2*g]);
                float c0 = s2.x, c1 = s2.y, c2 = s2.x, c3 = s2.y;
                const float* row = &bsc[(js + rsub)*PAD + g*Q4];
                if (DIM == 16){
                    float4 bf = *reinterpret_cast<const float4*>(row);
                    MMA_TF32(c0,c1,c2,c3, a0[0],a1[0],a2[0],a3[0],
                             __float_as_uint(bf.x), __float_as_uint(bf.y));
                    MMA_TF32(c0,c1,c2,c3, a0[KC-1],a1[KC-1],a2[KC-1],a3[KC-1],
                             __float_as_uint(bf.z), __float_as_uint(bf.w));
                } else {
                    float4 b1f = *reinterpret_cast<const float4*>(row);
                    float4 b2f = *reinterpret_cast<const float4*>(row + 4);
                    MMA_TF32(c0,c1,c2,c3, a0[0],a1[0],a2[0],a3[0],
                             __float_as_uint(b1f.x), __float_as_uint(b1f.y));
                    MMA_TF32(c0,c1,c2,c3, a0[1],a1[1],a2[1],a3[1],
                             __float_as_uint(b1f.z), __float_as_uint(b1f.w));
                    MMA_TF32(c0,c1,c2,c3, a0[KC-2],a1[KC-2],a2[KC-2],a3[KC-2],
                             __float_as_uint(b2f.x), __float_as_uint(b2f.y));
                    MMA_TF32(c0,c1,c2,c3, a0[KC-1],a1[KC-1],a2[KC-1],a3[KC-1],
                             __float_as_uint(b2f.z), __float_as_uint(b2f.w));
                }
                u32 j0 = (u32)(jt + js + 2*g);
                SA[st*2+0] = fpack(c0, j0);
                SA[st*2+1] = fpack(c1, j0+1);
                SB[st*2+0] = fpack(c2, j0);
                SB[st*2+1] = fpack(c3, j0+1);
            }
            sort8(SA); merge86(LA, SA);
            sort8(SB); merge86(LB, SB);
        }
        __syncthreads();
    }
    #undef STAGE

    if (r0 < n){
        int base = r0*CTOT + (p*NSUB + g)*KCAND;
#pragma unroll
        for (int k = 0; k < KCAND; k++) g_ci[base+k] = (int)(__float_as_uint(LA[k]) & 0x7FFFu);
    }
    if (r1 < n){
        int base = r1*CTOT + (p*NSUB + g)*KCAND;
#pragma unroll
        for (int k = 0; k < KCAND; k++) g_ci[base+k] = (int)(__float_as_uint(LB[k]) & 0x7FFFu);
    }
}

// ---------------- refine stage A: exact fp32 recompute, 8 threads/node ----------------
template<int DIM>
__global__ void refineA_kernel(const float* __restrict__ X, const float* __restrict__ sq,
                               int n){
    const int Q4 = DIM/4;
    int t = blockIdx.x*blockDim.x + threadIdx.x;
    int i = t >> 3;
    int s = t & 7;
    if (i >= n) return;
    float4 xi[Q4];
#pragma unroll
    for (int q = 0; q < Q4; q++) xi[q] = reinterpret_cast<const float4*>(X)[i*Q4 + q];

    float bd[KNN]; unsigned bi[KNN];
#pragma unroll
    for (int k = 0; k < KNN; k++){ bd[k] = INFINITY; bi[k] = 0xFFFFFFFFu; }

    int base = i*CTOT + s*CSLICE;
    for (int c = 0; c < CSLICE; c++){
        int jraw = g_ci[base+c];
        if (jraw >= n || jraw == i) continue;
        unsigned j = (unsigned)jraw;
        float dot = 0.f;
#pragma unroll
        for (int q = 0; q < Q4; q++){
            float4 xj = reinterpret_cast<const float4*>(X)[jraw*Q4 + q];
            dot = fmaf(xi[q].x, xj.x, dot);
            dot = fmaf(xi[q].y, xj.y, dot);
            dot = fmaf(xi[q].z, xj.z, dot);
            dot = fmaf(xi[q].w, xj.w, dot);
        }
        float e = fmaf(-2.f, dot, sq[jraw]);
        if (e < bd[KNN-1] || (e == bd[KNN-1] && j < bi[KNN-1])){
            bd[KNN-1] = e; bi[KNN-1] = j;
#pragma unroll
            for (int k = KNN-1; k > 0; k--){
                bool sw = (bd[k] < bd[k-1]) || (bd[k] == bd[k-1] && bi[k] < bi[k-1]);
                if (sw){
                    float td = bd[k]; bd[k] = bd[k-1]; bd[k-1] = td;
                    unsigned ti = bi[k]; bi[k] = bi[k-1]; bi[k-1] = ti;
                }
            }
        }
    }
    int ob = i*CMERGE + s*KNN;
#pragma unroll
    for (int k = 0; k < KNN; k++){ g_md[ob+k] = bd[k]; g_mi[ob+k] = (int)bi[k]; }
}

// ---------------- dynamic edge conv (fused candidate merge; optional cat0 + transpose folds) ----
template<int F, bool CAT, bool TR>
__global__ void edgeconv_kernel(const float* __restrict__ X,
                                const float* __restrict__ W1, const float* __restrict__ b1,
                                const float* __restrict__ W2, const float* __restrict__ b2,
                                int n, float* __restrict__ Y, float* __restrict__ sqout,
                                float* __restrict__ tout){
    __shared__ float sW1[2*F*32];
    __shared__ float sb1[32];
    __shared__ float sW2[32*32];
    __shared__ float sb2[32];
    for (int t = threadIdx.x; t < 2*F*32; t += blockDim.x) sW1[t] = W1[t];
    for (int t = threadIdx.x; t < 32*32;  t += blockDim.x) sW2[t] = W2[t];
    if (threadIdx.x < 32){ sb1[threadIdx.x] = b1[threadIdx.x]; sb2[threadIdx.x] = b2[threadIdx.x]; }
    __syncthreads();
    int i = blockIdx.x*blockDim.x + threadIdx.x;
    if (i >= n) return;

    // fused refineB: merge 48 exact (dist, idx) candidates -> top-6
    float bd[KNN]; unsigned bi[KNN];
#pragma unroll
    for (int k = 0; k < KNN; k++){ bd[k] = INFINITY; bi[k] = 0xFFFFFFFFu; }
    int mbase = i*CMERGE;
    for (int c = 0; c < CMERGE; c++){
        float d = g_md[mbase+c];
        unsigned j = (unsigned)g_mi[mbase+c];
        if (j == 0xFFFFFFFFu) continue;
        if (d < bd[KNN-1] || (d == bd[KNN-1] && j < bi[KNN-1])){
            bd[KNN-1] = d; bi[KNN-1] = j;
#pragma unroll
            for (int k = KNN-1; k > 0; k--){
                bool sw = (bd[k] < bd[k-1]) || (bd[k] == bd[k-1] && bi[k] < bi[k-1]);
                if (sw){
                    float td = bd[k]; bd[k] = bd[k-1]; bd[k-1] = td;
                    unsigned ti = bi[k]; bi[k] = bi[k-1]; bi[k-1] = ti;
                }
            }
        }
    }

    float base[32];
#pragma unroll
    for (int c = 0; c < 32; c++) base[c] = sb1[c];
    for (int d = 0; d < F; d++){
        float v = X[i*F+d];
#pragma unroll
        for (int c = 0; c < 32; c++) base[c] = fmaf(v, sW1[d*32+c], base[c]);
    }
    float acc[32];
#pragma unroll
    for (int c = 0; c < 32; c++) acc[c] = -INFINITY;

    for (int kk = 0; kk < KNN; kk++){
        int j = (int)bi[kk];
        float h[32];
#pragma unroll
        for (int c = 0; c < 32; c++) h[c] = base[c];
        for (int d = 0; d < F; d++){
            float v = X[j*F+d] - X[i*F+d];
#pragma unroll
            for (int c = 0; c < 32; c++) h[c] = fmaf(v, sW1[(F+d)*32+c], h[c]);
        }
#pragma unroll
        for (int c = 0; c < 32; c++) h[c] = fmaxf(h[c], 0.f);
#pragma unroll
        for (int c = 0; c < 32; c++){
            float o = sb2[c];
#pragma unroll
            for (int k = 0; k < 32; k++) o = fmaf(h[k], sW2[k*32+c], o);
            acc[c] = fmaxf(acc[c], o);
        }
    }
    float sqv = 0.f;
#pragma unroll
    for (int c = 0; c < 32; c++){
        float r = fmaxf(acc[c], 0.f);
        Y[i*32+c] = r;
        if (CAT){ g_cat0[i*48+16+c] = r; g_agg2[i*48+16+c] = r; }
        if (TR) tout[i*32 + (c&3)*8 + (c>>2)] = r;
        sqv = fmaf(r, r, sqv);
    }
    if (sqout) sqout[i] = sqv;
}

__global__ void scatter2_kernel(const int* __restrict__ src, const int* __restrict__ dst, int E){
    int t = blockIdx.x*blockDim.x + threadIdx.x;
    int e = t / 12;
    if (e >= E) return;
    int q = t % 12;
    int s = src[e], d = dst[e];
    float4 v = reinterpret_cast<const float4*>(g_cat0)[s*12 + q];
    float* a = &g_agg2[d*48 + q*4];
    atomicAdd(a+0, v.x); atomicAdd(a+1, v.y); atomicAdd(a+2, v.z); atomicAdd(a+3, v.w);
}

// ---------------- MLP layer 1 ----------------
__global__ void mlp1_kernel(const float* __restrict__ W, const float* __restrict__ b, int n){
    __shared__ float sW[96*96];
    __shared__ float sb[96];
    for (int t = threadIdx.x; t < 96*96; t += blockDim.x) sW[t] = W[t];
    for (int t = threadIdx.x; t < 96;    t += blockDim.x) sb[t] = b[t];
    __syncthreads();
    int i = blockIdx.x*blockDim.x + threadIdx.x;
    if (i >= n) return;
    float acc[96];
#pragma unroll
    for (int c = 0; c < 96; c++) acc[c] = sb[c];
    for (int d = 0; d < 64; d++){
        float v = g_x3[i*64+d];
#pragma unroll
        for (int c = 0; c < 96; c++) acc[c] = fmaf(v, sW[d*96+c], acc[c]);
    }
    for (int d = 0; d < 32; d++){
        float v = g_y2[i*32+d];
#pragma unroll
        for (int c = 0; c < 96; c++) acc[c] = fmaf(v, sW[(64+d)*96+c], acc[c]);
    }
#pragma unroll
    for (int c = 0; c < 96; c++) g_h1[i*96+c] = fmaxf(acc[c], 0.f);
}

// ---------------- MLP layers 2..out ----------------
__global__ void mlp2_kernel(const float* __restrict__ W2, const float* __restrict__ b2,
                            const float* __restrict__ W3, const float* __restrict__ b3,
                            const float* __restrict__ Wo, const float* __restrict__ bo,
                            int n, float* __restrict__ out){
    __shared__ float sW2[96*32]; __shared__ float sb2v[32];
    __shared__ float sW3[32*8];  __shared__ float sb3v[8];
    __shared__ float sWo[8];     __shared__ float sbo;
    for (int t = threadIdx.x; t < 96*32; t += blockDim.x) sW2[t] = W2[t];
    for (int t = threadIdx.x; t < 32*8;  t += blockDim.x) sW3[t] = W3[t];
    if (threadIdx.x < 32) sb2v[threadIdx.x] = b2[threadIdx.x];
    if (threadIdx.x < 8){ sb3v[threadIdx.x] = b3[threadIdx.x]; sWo[threadIdx.x] = Wo[threadIdx.x]; }
    if (threadIdx.x == 0) sbo = bo[0];
    __syncthreads();
    int i = blockIdx.x*blockDim.x + threadIdx.x;
    if (i >= n) return;
    float h[32];
#pragma unroll
    for (int c = 0; c < 32; c++) h[c] = sb2v[c];
    for (int d = 0; d < 96; d++){
        float v = g_h1[i*96+d];
#pragma unroll
        for (int c = 0; c < 32; c++) h[c] = fmaf(v, sW2[d*32+c], h[c]);
    }
#pragma unroll
    for (int c = 0; c < 32; c++) h[c] = fmaxf(h[c], 0.f);
    float g[8];
#pragma unroll
    for (int c = 0; c < 8; c++){
        float o = sb3v[c];
#pragma unroll
        for (int k = 0; k < 32; k++) o = fmaf(h[k], sW3[k*8+c], o);
        g[c] = fmaxf(o, 0.f);
    }
    float z = sbo;
#pragma unroll
    for (int c = 0; c < 8; c++) z = fmaf(g[c], sWo[c], z);
    out[i] = 1.0f / (1.0f + expf(-z));
}

// ---------------- launch ----------------
extern "C" void kernel_launch(void* const* d_in, const int* in_sizes, int n_in,
                              void* d_out, int out_size){
    const float* x   = (const float*)d_in[0];
    const int*   ei  = (const int*)  d_in[1];
    int n = in_sizes[0] / 16;
    int E = in_sizes[1] / 2;
    const int* src = ei;
    const int* dst = ei + E;

    const float* cW1 = (const float*)d_in[2];
    const float* cb1 = (const float*)d_in[5];
    const float* cW3 = (const float*)d_in[6];
    const float* cb3 = (const float*)d_in[9];
    const float* e1W1=(const float*)d_in[10]; const float* e1b1=(const float*)d_in[11];
    const float* e1W2=(const float*)d_in[12]; const float* e1b2=(const float*)d_in[13];
    const float* e2W1=(const float*)d_in[14]; const float* e2b1=(const float*)d_in[15];
    const float* e2W2=(const float*)d_in[16]; const float* e2b2=(const float*)d_in[17];
    const float* l1W =(const float*)d_in[18]; const float* l1b =(const float*)d_in[19];
    const float* l2W =(const float*)d_in[20]; const float* l2b =(const float*)d_in[21];
    const float* l3W =(const float*)d_in[22]; const float* l3b =(const float*)d_in[23];
    const float* oW  =(const float*)d_in[24]; const float* ob  =(const float*)d_in[25];
    float* out = (float*)d_out;

    void *p_agg1, *p_x1, *p_x1t, *p_sq1, *p_y1, *p_y1t, *p_sq2, *p_agg2, *p_x3, *p_y2;
    cudaGetSymbolAddress(&p_agg1, g_agg1);
    cudaGetSymbolAddress(&p_x1,   g_x1);
    cudaGetSymbolAddress(&p_x1t,  g_x1t);
    cudaGetSymbolAddress(&p_sq1,  g_sq1);
    cudaGetSymbolAddress(&p_y1,   g_y1);
    cudaGetSymbolAddress(&p_y1t,  g_y1t);
    cudaGetSymbolAddress(&p_sq2,  g_sq2);
    cudaGetSymbolAddress(&p_agg2, g_agg2);
    cudaGetSymbolAddress(&p_x3,   g_x3);
    cudaGetSymbolAddress(&p_y2,   g_y2);

    int nb = (n + 127) / 128;
    int tilesPerPart = (n + NPARTK*128 - 1) / (NPARTK*128);  // 11 for n=20000
    int chunk = tilesPerPart * 128;                          // 1408
    int npad = NPARTK * chunk;                               // 21120 <= NPAD
    dim3 knngrid(nb, NPARTK);
    int refA = (n*8 + 127) / 128;

    // FeaSt 1; x1 folded into cat0/agg2 AND transposed layout x1t
    init1_kernel<<<(n*16 + 255)/256, 256>>>(x, n, npad);
    scatter1_kernel<<<(E*4 + 255)/256, 256>>>(src, dst, x, E);
    feast_kernel<16,16,true,true,true><<<nb,128>>>((const float*)p_agg1, cW1, cb1, n,
                                                   (float*)p_x1, (float*)p_sq1, (float*)p_x1t);
    // kNN on x1: cp.async-pipelined tf32 MMA -> exact refine (merge fused in edgeconv)
    knn_mma_kernel<16,16><<<knngrid,256>>>((const float*)p_x1t, (const float*)p_sq1, n, chunk);
    refineA_kernel<16><<<refA,128>>>((const float*)p_x1, (const float*)p_sq1, n);
    edgeconv_kernel<16,true,true><<<nb,128>>>((const float*)p_x1,
                                              e1W1, e1b1, e1W2, e1b2, n,
                                              (float*)p_y1, (float*)p_sq2, (float*)p_y1t);
    // FeaSt 2 on cat0 = [x1|y1]
    scatter2_kernel<<<(E*12 + 255)/256, 256>>>(src, dst, E);
    feast_kernel<48,64,false,false,false><<<nb,128>>>((const float*)p_agg2, cW3, cb3, n,
                                                      (float*)p_x3, nullptr, nullptr);
    // kNN on y1
    knn_mma_kernel<32,36><<<knngrid,256>>>((const float*)p_y1t, (const float*)p_sq2, n, chunk);
    refineA_kernel<32><<<refA,128>>>((const float*)p_y1, (const float*)p_sq2, n);
    edgeconv_kernel<32,false,false><<<nb,128>>>((const float*)p_y1,
                                                e2W1, e2b1, e2W2, e2b2, n,
                                                (float*)p_y2, nullptr, nullptr);
    // Final MLP
    mlp1_kernel<<<nb,128>>>(l1W, l1b, n);
    mlp2_kernel<<<nb,128>>>(l2W, l2b, l3W, l3b, oW, ob, n, out);
}

// round 15
// speedup vs baseline: 1.2791x; 1.2791x over previous
#include <cuda_runtime.h>
#include <math.h>

#define NMAX 20000
#define NPAD 21120                 /* NPARTK * chunk (15 * 11 * 128) */
#define KNN 6
#define KCAND 6
#define NPARTK 15
#define NSUB 4
#define CTOT (NPARTK*NSUB*KCAND)   /* 360 candidate keys per node */
#define CSLICE (CTOT/8)            /* 45 per refine thread */
#define CMERGE 48                  /* 8 slices x 6 */

typedef unsigned int u32;

// ---------------- scratch (device globals; no allocation allowed) ----------------
__device__ __align__(16) float g_cnt [NMAX];
__device__ __align__(16) float g_agg1[NMAX*16];
__device__ __align__(16) float g_x1  [NMAX*16];
__device__ __align__(16) float g_x1t [NPAD*16];   /* zero-init pad rows never written */
__device__ __align__(16) float g_sq1 [NPAD];
__device__ __align__(16) float g_y1  [NMAX*32];
__device__ __align__(16) float g_y1t [NPAD*32];
__device__ __align__(16) float g_sq2 [NPAD];
__device__ __align__(16) float g_cat0[NMAX*48];
__device__ __align__(16) float g_agg2[NMAX*48];
__device__ __align__(16) float g_x3  [NMAX*64];
__device__ __align__(16) float g_y2  [NMAX*32];
__device__ __align__(16) float g_h1  [NMAX*96];
__device__ __align__(16) float g_ck  [NMAX*CTOT];  /* packed approx keys */
__device__ __align__(16) float g_md  [NMAX*CMERGE];
__device__ __align__(16) int   g_mi  [NMAX*CMERGE];

#define MMA_TF32(c0,c1,c2,c3,a0,a1,a2,a3,b0,b1) \
    asm volatile("mma.sync.aligned.m16n8k8.row.col.f32.tf32.tf32.f32 " \
        "{%0,%1,%2,%3}, {%4,%5,%6,%7}, {%8,%9}, {%0,%1,%2,%3};" \
        : "+f"(c0), "+f"(c1), "+f"(c2), "+f"(c3) \
        : "r"(a0), "r"(a1), "r"(a2), "r"(a3), "r"(b0), "r"(b1))

// cp.async helpers (LDGSTS)
__device__ __forceinline__ void cpa16(u32 dst, const void* src){
    asm volatile("cp.async.cg.shared.global [%0], [%1], 16;" :: "r"(dst), "l"(src));
}
#define CPA_COMMIT() asm volatile("cp.async.commit_group;")
#define CPA_WAIT1()  asm volatile("cp.async.wait_group 1;")
#define CPA_WAIT0()  asm volatile("cp.async.wait_group 0;")

// float key: distance mantissa truncated to high 17 bits, j spliced into low 15.
__device__ __forceinline__ float fpack(float e, u32 j){
    return __uint_as_float((__float_as_uint(e) & 0xFFFF8000u) | j);
}
#define KEY_INIT __uint_as_float(0x7F7FFFFFu)

#define CMPX(a,b) { float _lo = fminf(a,b); b = fmaxf(a,b); a = _lo; }

// branchless sorted insert into ascending 6-list (FMNMX only)
__device__ __forceinline__ void fbubble(float key, float r[KCAND]){
#pragma unroll
    for (int k = 0; k < KCAND; k++){
        float lo = fminf(r[k], key);
        key      = fmaxf(r[k], key);
        r[k] = lo;
    }
}

// Batcher odd-even mergesort network for 8 (19 comparators)
__device__ __forceinline__ void sort8(float s[8]){
    CMPX(s[0],s[1]); CMPX(s[2],s[3]); CMPX(s[4],s[5]); CMPX(s[6],s[7]);
    CMPX(s[0],s[2]); CMPX(s[1],s[3]); CMPX(s[4],s[6]); CMPX(s[5],s[7]);
    CMPX(s[1],s[2]); CMPX(s[5],s[6]);
    CMPX(s[0],s[4]); CMPX(s[1],s[5]); CMPX(s[2],s[6]); CMPX(s[3],s[7]);
    CMPX(s[2],s[4]); CMPX(s[3],s[5]);
    CMPX(s[1],s[2]); CMPX(s[3],s[4]); CMPX(s[5],s[6]);
}

// merge sorted L[6] with sorted s[8], keep lowest 6 sorted (bitonic halver).
__device__ __forceinline__ void merge86(float L[KCAND], const float s[8]){
    float t0 = fminf(L[0], s[5]);
    float t1 = fminf(L[1], s[4]);
    float t2 = fminf(L[2], s[3]);
    float t3 = fminf(L[3], s[2]);
    float t4 = fminf(L[4], s[1]);
    float t5 = fminf(L[5], s[0]);
    CMPX(t0,t3); CMPX(t1,t4); CMPX(t2,t5);
    CMPX(t0,t1); CMPX(t1,t2); CMPX(t0,t1);
    CMPX(t3,t4); CMPX(t4,t5); CMPX(t3,t4);
    L[0]=t0; L[1]=t1; L[2]=t2; L[3]=t3; L[4]=t4; L[5]=t5;
}

// ---------------- init: agg1 = x (self loop), cnt = 1, sq pads = 1e30 ----------------
__global__ void init1_kernel(const float* __restrict__ x, int n, int npad){
    int t = blockIdx.x*blockDim.x + threadIdx.x;
    if (t < n*16) g_agg1[t] = x[t];
    if (t < n)    g_cnt[t]  = 1.0f;
    if (t >= n && t < npad){ g_sq1[t] = 1e30f; g_sq2[t] = 1e30f; }
}

// ---------------- scatter-add of x[src] into agg1[dst], count edges ----------------
__global__ void scatter1_kernel(const int* __restrict__ src, const int* __restrict__ dst,
                                const float* __restrict__ x, int E){
    int t = blockIdx.x*blockDim.x + threadIdx.x;
    int e = t >> 2;
    if (e >= E) return;
    int q = t & 3;
    int s = src[e], d = dst[e];
    if (q == 0) atomicAdd(&g_cnt[d], 1.0f);
    float4 v = reinterpret_cast<const float4*>(x)[s*4 + q];
    float* a = &g_agg1[d*16 + q*4];
    atomicAdd(a+0, v.x); atomicAdd(a+1, v.y); atomicAdd(a+2, v.z); atomicAdd(a+3, v.w);
}

// ---------------- feast: out = relu((agg/cnt) @ W + b); optional sq/cat0/transpose folds --------
template<int IN, int OUT, bool WSQ, bool CAT, bool TR>
__global__ void feast_kernel(const float* __restrict__ agg, const float* __restrict__ W,
                             const float* __restrict__ b, int n,
                             float* __restrict__ out, float* __restrict__ sqout,
                             float* __restrict__ tout){
    __shared__ float sW[IN*OUT];
    __shared__ float sb[OUT];
    for (int t = threadIdx.x; t < IN*OUT; t += blockDim.x) sW[t] = W[t];
    for (int t = threadIdx.x; t < OUT;    t += blockDim.x) sb[t] = b[t];
    __syncthreads();
    int i = blockIdx.x*blockDim.x + threadIdx.x;
    if (i >= n) return;
    float inv = 1.0f / g_cnt[i];
    float acc[OUT];
#pragma unroll
    for (int c = 0; c < OUT; c++) acc[c] = sb[c];
    for (int d = 0; d < IN; d++){
        float v = agg[i*IN+d] * inv;
#pragma unroll
        for (int c = 0; c < OUT; c++) acc[c] = fmaf(v, sW[d*OUT+c], acc[c]);
    }
    float sq = 0.f;
#pragma unroll
    for (int c = 0; c < OUT; c++){
        float r = fmaxf(acc[c], 0.f);
        out[i*OUT+c] = r;
        if (CAT){ g_cat0[i*48+c] = r; g_agg2[i*48+c] = r; }
        if (TR) tout[i*OUT + (c&3)*(OUT/4) + (c>>2)] = r;
        sq = fmaf(r, r, sq);
    }
    if (WSQ) sqout[i] = sq;
}

// ---------------- tensor-core kNN: cp.async double-buffered, tf32 MMA, sorted selection --------
template<int DIM, int PAD>
__global__ void __launch_bounds__(256,4)
knn_mma_kernel(const float* __restrict__ Xt, const float* __restrict__ sq,
               int n, int chunk){
    const int KC = DIM/8;
    const int Q4 = DIM/4;
    __shared__ float bs[2][128*PAD];
    __shared__ float sqs[2][128];

    int tid = threadIdx.x;
    int w = tid >> 5;
    int lane = tid & 31;
    int g = lane & 3;
    int rsub = lane >> 2;
    int qbase = blockIdx.x*128 + w*16;
    int r0 = qbase + rsub;
    int r1 = r0 + 8;
    int p = blockIdx.y;
    int jbeg = p * chunk;
    int T = chunk >> 7;

    int rr0 = min(r0, n-1), rr1 = min(r1, n-1);
    u32 a0[KC], a1[KC], a2[KC], a3[KC];
    {
        const float2* xa = (const float2*)(Xt + (size_t)rr0*DIM) + g*(Q4/2);
        const float2* xb = (const float2*)(Xt + (size_t)rr1*DIM) + g*(Q4/2);
#pragma unroll
        for (int kc = 0; kc < KC; kc++){
            float2 va = xa[kc], vb = xb[kc];
            a0[kc] = __float_as_uint(-2.0f * va.x);
            a2[kc] = __float_as_uint(-2.0f * va.y);
            a1[kc] = __float_as_uint(-2.0f * vb.x);
            a3[kc] = __float_as_uint(-2.0f * vb.y);
        }
    }

    u32 sb0 = (u32)__cvta_generic_to_shared(&bs[0][0]);
    u32 sb1 = (u32)__cvta_generic_to_shared(&bs[1][0]);
    u32 sq0 = (u32)__cvta_generic_to_shared(&sqs[0][0]);
    u32 sq1 = (u32)__cvta_generic_to_shared(&sqs[1][0]);

    float LA[KCAND], LB[KCAND];
#pragma unroll
    for (int k = 0; k < KCAND; k++){ LA[k] = KEY_INIT; LB[k] = KEY_INIT; }

    #define STAGE(BUF, JT) { \
        u32 _bb = (BUF) ? sb1 : sb0; \
        u32 _bq = (BUF) ? sq1 : sq0; \
        _Pragma("unroll") \
        for (int idx = tid; idx < 128*Q4; idx += 256){ \
            int jr = idx / Q4, q = idx - jr*Q4; \
            cpa16(_bb + (u32)(jr*PAD + q*4)*4u, Xt + (size_t)((JT)+jr)*DIM + q*4); \
        } \
        if (tid < 32) cpa16(_bq + tid*16u, sq + (JT) + tid*4); \
    }

    STAGE(0, jbeg);
    CPA_COMMIT();

    for (int t = 0; t < T; t++){
        int cur = t & 1;
        if (t + 1 < T){
            STAGE(1-cur, jbeg + (t+1)*128);
            CPA_COMMIT();
            CPA_WAIT1();
        } else {
            CPA_WAIT0();
        }
        __syncthreads();

        const float* bsc = &bs[cur][0];
        const float* sqc = &sqs[cur][0];
        int jt = jbeg + t*128;

#pragma unroll
        for (int jg = 0; jg < 128; jg += 32){
            float SA[8], SB[8];
#pragma unroll
            for (int st = 0; st < 4; st++){
                int js = jg + st*8;
                float2 s2 = *reinterpret_cast<const float2*>(&sqc[js + 2*g]);
                float c0 = s2.x, c1 = s2.y, c2 = s2.x, c3 = s2.y;
                const float* row = &bsc[(js + rsub)*PAD + g*Q4];
                if (DIM == 16){
                    float4 bf = *reinterpret_cast<const float4*>(row);
                    MMA_TF32(c0,c1,c2,c3, a0[0],a1[0],a2[0],a3[0],
                             __float_as_uint(bf.x), __float_as_uint(bf.y));
                    MMA_TF32(c0,c1,c2,c3, a0[KC-1],a1[KC-1],a2[KC-1],a3[KC-1],
                             __float_as_uint(bf.z), __float_as_uint(bf.w));
                } else {
                    float4 b1f = *reinterpret_cast<const float4*>(row);
                    float4 b2f = *reinterpret_cast<const float4*>(row + 4);
                    MMA_TF32(c0,c1,c2,c3, a0[0],a1[0],a2[0],a3[0],
                             __float_as_uint(b1f.x), __float_as_uint(b1f.y));
                    MMA_TF32(c0,c1,c2,c3, a0[1],a1[1],a2[1],a3[1],
                             __float_as_uint(b1f.z), __float_as_uint(b1f.w));
                    MMA_TF32(c0,c1,c2,c3, a0[KC-2],a1[KC-2],a2[KC-2],a3[KC-2],
                             __float_as_uint(b2f.x), __float_as_uint(b2f.y));
                    MMA_TF32(c0,c1,c2,c3, a0[KC-1],a1[KC-1],a2[KC-1],a3[KC-1],
                             __float_as_uint(b2f.z), __float_as_uint(b2f.w));
                }
                u32 j0 = (u32)(jt + js + 2*g);
                SA[st*2+0] = fpack(c0, j0);
                SA[st*2+1] = fpack(c1, j0+1);
                SB[st*2+0] = fpack(c2, j0);
                SB[st*2+1] = fpack(c3, j0+1);
            }
            sort8(SA); merge86(LA, SA);
            sort8(SB); merge86(LB, SB);
        }
        __syncthreads();
    }
    #undef STAGE

    if (r0 < n){
        int base = r0*CTOT + (p*NSUB + g)*KCAND;
#pragma unroll
        for (int k = 0; k < KCAND; k++) g_ck[base+k] = LA[k];
    }
    if (r1 < n){
        int base = r1*CTOT + (p*NSUB + g)*KCAND;
#pragma unroll
        for (int k = 0; k < KCAND; k++) g_ck[base+k] = LB[k];
    }
}

// ---------------- refine stage A: approx-prune 45 keys -> 6, exact-refine only those ----------
template<int DIM>
__global__ void refineA_kernel(const float* __restrict__ X, const float* __restrict__ sq,
                               int n){
    const int Q4 = DIM/4;
    int t = blockIdx.x*blockDim.x + threadIdx.x;
    int i = t >> 3;
    int s = t & 7;
    if (i >= n) return;

    // 1) branchless approx top-6 over this thread's 45 keys (coalesced stream, no gather)
    float L[KCAND];
#pragma unroll
    for (int k = 0; k < KCAND; k++) L[k] = KEY_INIT;
    const float* kp = g_ck + (size_t)i*CTOT + s*CSLICE;
#pragma unroll 5
    for (int c = 0; c < CSLICE; c++) fbubble(kp[c], L);

    // 2) exact fp32 distance for the 6 local winners only
    float4 xi[Q4];
#pragma unroll
    for (int q = 0; q < Q4; q++) xi[q] = reinterpret_cast<const float4*>(X)[i*Q4 + q];

    int ob = i*CMERGE + s*KNN;
#pragma unroll
    for (int k = 0; k < KNN; k++){
        u32 j = __float_as_uint(L[k]) & 0x7FFFu;
        float e = INFINITY;
        u32 jo = 0xFFFFFFFFu;
        if ((int)j < n && (int)j != i){
            float dot = 0.f;
#pragma unroll
            for (int q = 0; q < Q4; q++){
                float4 xj = reinterpret_cast<const float4*>(X)[j*Q4 + q];
                dot = fmaf(xi[q].x, xj.x, dot);
                dot = fmaf(xi[q].y, xj.y, dot);
                dot = fmaf(xi[q].z, xj.z, dot);
                dot = fmaf(xi[q].w, xj.w, dot);
            }
            e = fmaf(-2.f, dot, sq[j]);
            jo = j;
        }
        g_md[ob+k] = e;
        g_mi[ob+k] = (int)jo;
    }
}

// ---------------- dynamic edge conv (fused candidate merge; optional cat0 + transpose folds) ----
template<int F, bool CAT, bool TR>
__global__ void edgeconv_kernel(const float* __restrict__ X,
                                const float* __restrict__ W1, const float* __restrict__ b1,
                                const float* __restrict__ W2, const float* __restrict__ b2,
                                int n, float* __restrict__ Y, float* __restrict__ sqout,
                                float* __restrict__ tout){
    __shared__ float sW1[2*F*32];
    __shared__ float sb1[32];
    __shared__ float sW2[32*32];
    __shared__ float sb2[32];
    for (int t = threadIdx.x; t < 2*F*32; t += blockDim.x) sW1[t] = W1[t];
    for (int t = threadIdx.x; t < 32*32;  t += blockDim.x) sW2[t] = W2[t];
    if (threadIdx.x < 32){ sb1[threadIdx.x] = b1[threadIdx.x]; sb2[threadIdx.x] = b2[threadIdx.x]; }
    __syncthreads();
    int i = blockIdx.x*blockDim.x + threadIdx.x;
    if (i >= n) return;

    // fused refineB: merge 48 exact (dist, idx) candidates -> top-6 (duplicates across
    // slices are impossible: each j lives in exactly one (partition, residue) bucket)
    float bd[KNN]; unsigned bi[KNN];
#pragma unroll
    for (int k = 0; k < KNN; k++){ bd[k] = INFINITY; bi[k] = 0xFFFFFFFFu; }
    int mbase = i*CMERGE;
    for (int c = 0; c < CMERGE; c++){
        float d = g_md[mbase+c];
        unsigned j = (unsigned)g_mi[mbase+c];
        if (j == 0xFFFFFFFFu) continue;
        if (d < bd[KNN-1] || (d == bd[KNN-1] && j < bi[KNN-1])){
            bd[KNN-1] = d; bi[KNN-1] = j;
#pragma unroll
            for (int k = KNN-1; k > 0; k--){
                bool sw = (bd[k] < bd[k-1]) || (bd[k] == bd[k-1] && bi[k] < bi[k-1]);
                if (sw){
                    float td = bd[k]; bd[k] = bd[k-1]; bd[k-1] = td;
                    unsigned ti = bi[k]; bi[k] = bi[k-1]; bi[k-1] = ti;
                }
            }
        }
    }

    float base[32];
#pragma unroll
    for (int c = 0; c < 32; c++) base[c] = sb1[c];
    for (int d = 0; d < F; d++){
        float v = X[i*F+d];
#pragma unroll
        for (int c = 0; c < 32; c++) base[c] = fmaf(v, sW1[d*32+c], base[c]);
    }
    float acc[32];
#pragma unroll
    for (int c = 0; c < 32; c++) acc[c] = -INFINITY;

    for (int kk = 0; kk < KNN; kk++){
        int j = (int)bi[kk];
        float h[32];
#pragma unroll
        for (int c = 0; c < 32; c++) h[c] = base[c];
        for (int d = 0; d < F; d++){
            float v = X[j*F+d] - X[i*F+d];
#pragma unroll
            for (int c = 0; c < 32; c++) h[c] = fmaf(v, sW1[(F+d)*32+c], h[c]);
        }
#pragma unroll
        for (int c = 0; c < 32; c++) h[c] = fmaxf(h[c], 0.f);
#pragma unroll
        for (int c = 0; c < 32; c++){
            float o = sb2[c];
#pragma unroll
            for (int k = 0; k < 32; k++) o = fmaf(h[k], sW2[k*32+c], o);
            acc[c] = fmaxf(acc[c], o);
        }
    }
    float sqv = 0.f;
#pragma unroll
    for (int c = 0; c < 32; c++){
        float r = fmaxf(acc[c], 0.f);
        Y[i*32+c] = r;
        if (CAT){ g_cat0[i*48+16+c] = r; g_agg2[i*48+16+c] = r; }
        if (TR) tout[i*32 + (c&3)*8 + (c>>2)] = r;
        sqv = fmaf(r, r, sqv);
    }
    if (sqout) sqout[i] = sqv;
}

__global__ void scatter2_kernel(const int* __restrict__ src, const int* __restrict__ dst, int E){
    int t = blockIdx.x*blockDim.x + threadIdx.x;
    int e = t / 12;
    if (e >= E) return;
    int q = t % 12;
    int s = src[e], d = dst[e];
    float4 v = reinterpret_cast<const float4*>(g_cat0)[s*12 + q];
    float* a = &g_agg2[d*48 + q*4];
    atomicAdd(a+0, v.x); atomicAdd(a+1, v.y); atomicAdd(a+2, v.z); atomicAdd(a+3, v.w);
}

// ---------------- MLP layer 1 ----------------
__global__ void mlp1_kernel(const float* __restrict__ W, const float* __restrict__ b, int n){
    __shared__ float sW[96*96];
    __shared__ float sb[96];
    for (int t = threadIdx.x; t < 96*96; t += blockDim.x) sW[t] = W[t];
    for (int t = threadIdx.x; t < 96;    t += blockDim.x) sb[t] = b[t];
    __syncthreads();
    int i = blockIdx.x*blockDim.x + threadIdx.x;
    if (i >= n) return;
    float acc[96];
#pragma unroll
    for (int c = 0; c < 96; c++) acc[c] = sb[c];
    for (int d = 0; d < 64; d++){
        float v = g_x3[i*64+d];
#pragma unroll
        for (int c = 0; c < 96; c++) acc[c] = fmaf(v, sW[d*96+c], acc[c]);
    }
    for (int d = 0; d < 32; d++){
        float v = g_y2[i*32+d];
#pragma unroll
        for (int c = 0; c < 96; c++) acc[c] = fmaf(v, sW[(64+d)*96+c], acc[c]);
    }
#pragma unroll
    for (int c = 0; c < 96; c++) g_h1[i*96+c] = fmaxf(acc[c], 0.f);
}

// ---------------- MLP layers 2..out ----------------
__global__ void mlp2_kernel(const float* __restrict__ W2, const float* __restrict__ b2,
                            const float* __restrict__ W3, const float* __restrict__ b3,
                            const float* __restrict__ Wo, const float* __restrict__ bo,
                            int n, float* __restrict__ out){
    __shared__ float sW2[96*32]; __shared__ float sb2v[32];
    __shared__ float sW3[32*8];  __shared__ float sb3v[8];
    __shared__ float sWo[8];     __shared__ float sbo;
    for (int t = threadIdx.x; t < 96*32; t += blockDim.x) sW2[t] = W2[t];
    for (int t = threadIdx.x; t < 32*8;  t += blockDim.x) sW3[t] = W3[t];
    if (threadIdx.x < 32) sb2v[threadIdx.x] = b2[threadIdx.x];
    if (threadIdx.x < 8){ sb3v[threadIdx.x] = b3[threadIdx.x]; sWo[threadIdx.x] = Wo[threadIdx.x]; }
    if (threadIdx.x == 0) sbo = bo[0];
    __syncthreads();
    int i = blockIdx.x*blockDim.x + threadIdx.x;
    if (i >= n) return;
    float h[32];
#pragma unroll
    for (int c = 0; c < 32; c++) h[c] = sb2v[c];
    for (int d = 0; d < 96; d++){
        float v = g_h1[i*96+d];
#pragma unroll
        for (int c = 0; c < 32; c++) h[c] = fmaf(v, sW2[d*32+c], h[c]);
    }
#pragma unroll
    for (int c = 0; c < 32; c++) h[c] = fmaxf(h[c], 0.f);
    float g[8];
#pragma unroll
    for (int c = 0; c < 8; c++){
        float o = sb3v[c];
#pragma unroll
        for (int k = 0; k < 32; k++) o = fmaf(h[k], sW3[k*8+c], o);
        g[c] = fmaxf(o, 0.f);
    }
    float z = sbo;
#pragma unroll
    for (int c = 0; c < 8; c++) z = fmaf(g[c], sWo[c], z);
    out[i] = 1.0f / (1.0f + expf(-z));
}

// ---------------- launch ----------------
extern "C" void kernel_launch(void* const* d_in, const int* in_sizes, int n_in,
                              void* d_out, int out_size){
    const float* x   = (const float*)d_in[0];
    const int*   ei  = (const int*)  d_in[1];
    int n = in_sizes[0] / 16;
    int E = in_sizes[1] / 2;
    const int* src = ei;
    const int* dst = ei + E;

    const float* cW1 = (const float*)d_in[2];
    const float* cb1 = (const float*)d_in[5];
    const float* cW3 = (const float*)d_in[6];
    const float* cb3 = (const float*)d_in[9];
    const float* e1W1=(const float*)d_in[10]; const float* e1b1=(const float*)d_in[11];
    const float* e1W2=(const float*)d_in[12]; const float* e1b2=(const float*)d_in[13];
    const float* e2W1=(const float*)d_in[14]; const float* e2b1=(const float*)d_in[15];
    const float* e2W2=(const float*)d_in[16]; const float* e2b2=(const float*)d_in[17];
    const float* l1W =(const float*)d_in[18]; const float* l1b =(const float*)d_in[19];
    const float* l2W =(const float*)d_in[20]; const float* l2b =(const float*)d_in[21];
    const float* l3W =(const float*)d_in[22]; const float* l3b =(const float*)d_in[23];
    const float* oW  =(const float*)d_in[24]; const float* ob  =(const float*)d_in[25];
    float* out = (float*)d_out;

    void *p_agg1, *p_x1, *p_x1t, *p_sq1, *p_y1, *p_y1t, *p_sq2, *p_agg2, *p_x3, *p_y2;
    cudaGetSymbolAddress(&p_agg1, g_agg1);
    cudaGetSymbolAddress(&p_x1,   g_x1);
    cudaGetSymbolAddress(&p_x1t,  g_x1t);
    cudaGetSymbolAddress(&p_sq1,  g_sq1);
    cudaGetSymbolAddress(&p_y1,   g_y1);
    cudaGetSymbolAddress(&p_y1t,  g_y1t);
    cudaGetSymbolAddress(&p_sq2,  g_sq2);
    cudaGetSymbolAddress(&p_agg2, g_agg2);
    cudaGetSymbolAddress(&p_x3,   g_x3);
    cudaGetSymbolAddress(&p_y2,   g_y2);

    int nb = (n + 127) / 128;
    int tilesPerPart = (n + NPARTK*128 - 1) / (NPARTK*128);  // 11 for n=20000
    int chunk = tilesPerPart * 128;                          // 1408
    int npad = NPARTK * chunk;                               // 21120 <= NPAD
    dim3 knngrid(nb, NPARTK);
    int refA = (n*8 + 127) / 128;

    // FeaSt 1; x1 folded into cat0/agg2 AND transposed layout x1t
    init1_kernel<<<(n*16 + 255)/256, 256>>>(x, n, npad);
    scatter1_kernel<<<(E*4 + 255)/256, 256>>>(src, dst, x, E);
    feast_kernel<16,16,true,true,true><<<nb,128>>>((const float*)p_agg1, cW1, cb1, n,
                                                   (float*)p_x1, (float*)p_sq1, (float*)p_x1t);
    // kNN on x1: cp.async-pipelined tf32 MMA -> prune+exact refine (merge fused in edgeconv)
    knn_mma_kernel<16,16><<<knngrid,256>>>((const float*)p_x1t, (const float*)p_sq1, n, chunk);
    refineA_kernel<16><<<refA,128>>>((const float*)p_x1, (const float*)p_sq1, n);
    edgeconv_kernel<16,true,true><<<nb,128>>>((const float*)p_x1,
                                              e1W1, e1b1, e1W2, e1b2, n,
                                              (float*)p_y1, (float*)p_sq2, (float*)p_y1t);
    // FeaSt 2 on cat0 = [x1|y1]
    scatter2_kernel<<<(E*12 + 255)/256, 256>>>(src, dst, E);
    feast_kernel<48,64,false,false,false><<<nb,128>>>((const float*)p_agg2, cW3, cb3, n,
                                                      (float*)p_x3, nullptr, nullptr);
    // kNN on y1
    knn_mma_kernel<32,36><<<knngrid,256>>>((const float*)p_y1t, (const float*)p_sq2, n, chunk);
    refineA_kernel<32><<<refA,128>>>((const float*)p_y1, (const float*)p_sq2, n);
    edgeconv_kernel<32,false,false><<<nb,128>>>((const float*)p_y1,
                                                e2W1, e2b1, e2W2, e2b2, n,
                                                (float*)p_y2, nullptr, nullptr);
    // Final MLP
    mlp1_kernel<<<nb,128>>>(l1W, l1b, n);
    mlp2_kernel<<<nb,128>>>(l2W, l2b, l3W, l3b, oW, ob, n, out);
}

// round 16
// speedup vs baseline: 1.4044x; 1.0980x over previous
#include <cuda_runtime.h>
#include <math.h>

#define NMAX 20000
#define NPAD 21120                 /* NPARTK * chunk (15 * 11 * 128) */
#define KNN 6
#define KSEL 4                     /* per-bucket approx list depth */
#define REFK 6                     /* refine prune depth */
#define NPARTK 15
#define NSUB 4
#define CTOT (NPARTK*NSUB*KSEL)    /* 240 candidate keys per node */
#define CSLICE (CTOT/8)            /* 30 per refine thread */
#define CMERGE 48                  /* 8 slices x 6 */

typedef unsigned int u32;

// ---------------- scratch (device globals; no allocation allowed) ----------------
__device__ __align__(16) float g_cnt [NMAX];
__device__ __align__(16) float g_agg1[NMAX*16];
__device__ __align__(16) float g_x1  [NMAX*16];
__device__ __align__(16) float g_x1t [NPAD*16];   /* zero-init pad rows never written */
__device__ __align__(16) float g_sq1 [NPAD];
__device__ __align__(16) float g_y1  [NMAX*32];
__device__ __align__(16) float g_y1t [NPAD*32];
__device__ __align__(16) float g_sq2 [NPAD];
__device__ __align__(16) float g_cat0[NMAX*48];
__device__ __align__(16) float g_agg2[NMAX*48];
__device__ __align__(16) float g_x3  [NMAX*64];
__device__ __align__(16) float g_y2  [NMAX*32];
__device__ __align__(16) float g_h1  [NMAX*96];
__device__ __align__(16) float g_ck  [NMAX*CTOT];  /* packed approx keys */
__device__ __align__(16) float g_md  [NMAX*CMERGE];
__device__ __align__(16) int   g_mi  [NMAX*CMERGE];

#define MMA_TF32(c0,c1,c2,c3,a0,a1,a2,a3,b0,b1) \
    asm volatile("mma.sync.aligned.m16n8k8.row.col.f32.tf32.tf32.f32 " \
        "{%0,%1,%2,%3}, {%4,%5,%6,%7}, {%8,%9}, {%0,%1,%2,%3};" \
        : "+f"(c0), "+f"(c1), "+f"(c2), "+f"(c3) \
        : "r"(a0), "r"(a1), "r"(a2), "r"(a3), "r"(b0), "r"(b1))

// cp.async helpers (LDGSTS)
__device__ __forceinline__ void cpa16(u32 dst, const void* src){
    asm volatile("cp.async.cg.shared.global [%0], [%1], 16;" :: "r"(dst), "l"(src));
}
#define CPA_COMMIT() asm volatile("cp.async.commit_group;")
#define CPA_WAIT1()  asm volatile("cp.async.wait_group 1;")
#define CPA_WAIT0()  asm volatile("cp.async.wait_group 0;")

// vector reduction: 4 floats, one L2 transaction (sm_90+)
__device__ __forceinline__ void red4(float* a, float4 v){
    asm volatile("red.global.add.v4.f32 [%0], {%1, %2, %3, %4};"
        :: "l"(a), "f"(v.x), "f"(v.y), "f"(v.z), "f"(v.w) : "memory");
}

// float key: distance mantissa truncated to high 17 bits, j spliced into low 15.
__device__ __forceinline__ float fpack(float e, u32 j){
    return __uint_as_float((__float_as_uint(e) & 0xFFFF8000u) | j);
}
#define KEY_INIT __uint_as_float(0x7F7FFFFFu)

#define CMPX(a,b) { float _lo = fminf(a,b); b = fmaxf(a,b); a = _lo; }

// branchless sorted insert into ascending REFK-list (FMNMX only)
__device__ __forceinline__ void fbubble6(float key, float r[REFK]){
#pragma unroll
    for (int k = 0; k < REFK; k++){
        float lo = fminf(r[k], key);
        key      = fmaxf(r[k], key);
        r[k] = lo;
    }
}

// Batcher odd-even mergesort network for 8 (19 comparators)
__device__ __forceinline__ void sort8(float s[8]){
    CMPX(s[0],s[1]); CMPX(s[2],s[3]); CMPX(s[4],s[5]); CMPX(s[6],s[7]);
    CMPX(s[0],s[2]); CMPX(s[1],s[3]); CMPX(s[4],s[6]); CMPX(s[5],s[7]);
    CMPX(s[1],s[2]); CMPX(s[5],s[6]);
    CMPX(s[0],s[4]); CMPX(s[1],s[5]); CMPX(s[2],s[6]); CMPX(s[3],s[7]);
    CMPX(s[2],s[4]); CMPX(s[3],s[5]);
    CMPX(s[1],s[2]); CMPX(s[3],s[4]); CMPX(s[5],s[6]);
}

// merge sorted L[4] with sorted s[8], keep lowest 4 sorted.
// s[4..7] have >=5 elements <= them, so they cannot reach the lowest 4.
// Bitonic halver over L[0..3] ++ reverse(s[0..3]), then bitonic sort-4.
__device__ __forceinline__ void merge84(float L[KSEL], const float s[8]){
    float t0 = fminf(L[0], s[3]);
    float t1 = fminf(L[1], s[2]);
    float t2 = fminf(L[2], s[1]);
    float t3 = fminf(L[3], s[0]);
    CMPX(t0,t2); CMPX(t1,t3);
    CMPX(t0,t1); CMPX(t2,t3);
    L[0]=t0; L[1]=t1; L[2]=t2; L[3]=t3;
}

// ---------------- init: agg1 = x (self loop), cnt = 1, sq pads = 1e30 ----------------
__global__ void init1_kernel(const float* __restrict__ x, int n, int npad){
    int t = blockIdx.x*blockDim.x + threadIdx.x;
    if (t < n*16) g_agg1[t] = x[t];
    if (t < n)    g_cnt[t]  = 1.0f;
    if (t >= n && t < npad){ g_sq1[t] = 1e30f; g_sq2[t] = 1e30f; }
}

// ---------------- scatter-add of x[src] into agg1[dst] (v4 red), count edges ----------------
__global__ void scatter1_kernel(const int* __restrict__ src, const int* __restrict__ dst,
                                const float* __restrict__ x, int E){
    int t = blockIdx.x*blockDim.x + threadIdx.x;
    int e = t >> 2;
    if (e >= E) return;
    int q = t & 3;
    int s = src[e], d = dst[e];
    if (q == 0) atomicAdd(&g_cnt[d], 1.0f);
    float4 v = reinterpret_cast<const float4*>(x)[s*4 + q];
    red4(&g_agg1[d*16 + q*4], v);
}

// ---------------- feast: out = relu((agg/cnt) @ W + b); optional sq/cat0/transpose folds --------
template<int IN, int OUT, bool WSQ, bool CAT, bool TR>
__global__ void feast_kernel(const float* __restrict__ agg, const float* __restrict__ W,
                             const float* __restrict__ b, int n,
                             float* __restrict__ out, float* __restrict__ sqout,
                             float* __restrict__ tout){
    __shared__ float sW[IN*OUT];
    __shared__ float sb[OUT];
    for (int t = threadIdx.x; t < IN*OUT; t += blockDim.x) sW[t] = W[t];
    for (int t = threadIdx.x; t < OUT;    t += blockDim.x) sb[t] = b[t];
    __syncthreads();
    int i = blockIdx.x*blockDim.x + threadIdx.x;
    if (i >= n) return;
    float inv = 1.0f / g_cnt[i];
    float acc[OUT];
#pragma unroll
    for (int c = 0; c < OUT; c++) acc[c] = sb[c];
    for (int d = 0; d < IN; d++){
        float v = agg[i*IN+d] * inv;
#pragma unroll
        for (int c = 0; c < OUT; c++) acc[c] = fmaf(v, sW[d*OUT+c], acc[c]);
    }
    float sq = 0.f;
#pragma unroll
    for (int c = 0; c < OUT; c++){
        float r = fmaxf(acc[c], 0.f);
        out[i*OUT+c] = r;
        if (CAT){ g_cat0[i*48+c] = r; g_agg2[i*48+c] = r; }
        if (TR) tout[i*OUT + (c&3)*(OUT/4) + (c>>2)] = r;
        sq = fmaf(r, r, sq);
    }
    if (WSQ) sqout[i] = sq;
}

// ---------------- tensor-core kNN: cp.async double-buffered, tf32 MMA, sorted selection --------
template<int DIM, int PAD>
__global__ void __launch_bounds__(256,4)
knn_mma_kernel(const float* __restrict__ Xt, const float* __restrict__ sq,
               int n, int chunk){
    const int KC = DIM/8;
    const int Q4 = DIM/4;
    __shared__ float bs[2][128*PAD];
    __shared__ float sqs[2][128];

    int tid = threadIdx.x;
    int w = tid >> 5;
    int lane = tid & 31;
    int g = lane & 3;
    int rsub = lane >> 2;
    int qbase = blockIdx.x*128 + w*16;
    int r0 = qbase + rsub;
    int r1 = r0 + 8;
    int p = blockIdx.y;
    int jbeg = p * chunk;
    int T = chunk >> 7;

    int rr0 = min(r0, n-1), rr1 = min(r1, n-1);
    u32 a0[KC], a1[KC], a2[KC], a3[KC];
    {
        const float2* xa = (const float2*)(Xt + (size_t)rr0*DIM) + g*(Q4/2);
        const float2* xb = (const float2*)(Xt + (size_t)rr1*DIM) + g*(Q4/2);
#pragma unroll
        for (int kc = 0; kc < KC; kc++){
            float2 va = xa[kc], vb = xb[kc];
            a0[kc] = __float_as_uint(-2.0f * va.x);
            a2[kc] = __float_as_uint(-2.0f * va.y);
            a1[kc] = __float_as_uint(-2.0f * vb.x);
            a3[kc] = __float_as_uint(-2.0f * vb.y);
        }
    }

    u32 sb0 = (u32)__cvta_generic_to_shared(&bs[0][0]);
    u32 sb1 = (u32)__cvta_generic_to_shared(&bs[1][0]);
    u32 sq0 = (u32)__cvta_generic_to_shared(&sqs[0][0]);
    u32 sq1 = (u32)__cvta_generic_to_shared(&sqs[1][0]);

    float LA[KSEL], LB[KSEL];
#pragma unroll
    for (int k = 0; k < KSEL; k++){ LA[k] = KEY_INIT; LB[k] = KEY_INIT; }

    #define STAGE(BUF, JT) { \
        u32 _bb = (BUF) ? sb1 : sb0; \
        u32 _bq = (BUF) ? sq1 : sq0; \
        _Pragma("unroll") \
        for (int idx = tid; idx < 128*Q4; idx += 256){ \
            int jr = idx / Q4, q = idx - jr*Q4; \
            cpa16(_bb + (u32)(jr*PAD + q*4)*4u, Xt + (size_t)((JT)+jr)*DIM + q*4); \
        } \
        if (tid < 32) cpa16(_bq + tid*16u, sq + (JT) + tid*4); \
    }

    STAGE(0, jbeg);
    CPA_COMMIT();

    for (int t = 0; t < T; t++){
        int cur = t & 1;
        if (t + 1 < T){
            STAGE(1-cur, jbeg + (t+1)*128);
            CPA_COMMIT();
            CPA_WAIT1();
        } else {
            CPA_WAIT0();
        }
        __syncthreads();

        const float* bsc = &bs[cur][0];
        const float* sqc = &sqs[cur][0];
        int jt = jbeg + t*128;

#pragma unroll
        for (int jg = 0; jg < 128; jg += 32){
            float SA[8], SB[8];
#pragma unroll
            for (int st = 0; st < 4; st++){
                int js = jg + st*8;
                float2 s2 = *reinterpret_cast<const float2*>(&sqc[js + 2*g]);
                float c0 = s2.x, c1 = s2.y, c2 = s2.x, c3 = s2.y;
                const float* row = &bsc[(js + rsub)*PAD + g*Q4];
                if (DIM == 16){
                    float4 bf = *reinterpret_cast<const float4*>(row);
                    MMA_TF32(c0,c1,c2,c3, a0[0],a1[0],a2[0],a3[0],
                             __float_as_uint(bf.x), __float_as_uint(bf.y));
                    MMA_TF32(c0,c1,c2,c3, a0[KC-1],a1[KC-1],a2[KC-1],a3[KC-1],
                             __float_as_uint(bf.z), __float_as_uint(bf.w));
                } else {
                    float4 b1f = *reinterpret_cast<const float4*>(row);
                    float4 b2f = *reinterpret_cast<const float4*>(row + 4);
                    MMA_TF32(c0,c1,c2,c3, a0[0],a1[0],a2[0],a3[0],
                             __float_as_uint(b1f.x), __float_as_uint(b1f.y));
                    MMA_TF32(c0,c1,c2,c3, a0[1],a1[1],a2[1],a3[1],
                             __float_as_uint(b1f.z), __float_as_uint(b1f.w));
                    MMA_TF32(c0,c1,c2,c3, a0[KC-2],a1[KC-2],a2[KC-2],a3[KC-2],
                             __float_as_uint(b2f.x), __float_as_uint(b2f.y));
                    MMA_TF32(c0,c1,c2,c3, a0[KC-1],a1[KC-1],a2[KC-1],a3[KC-1],
                             __float_as_uint(b2f.z), __float_as_uint(b2f.w));
                }
                u32 j0 = (u32)(jt + js + 2*g);
                SA[st*2+0] = fpack(c0, j0);
                SA[st*2+1] = fpack(c1, j0+1);
                SB[st*2+0] = fpack(c2, j0);
                SB[st*2+1] = fpack(c3, j0+1);
            }
            sort8(SA); merge84(LA, SA);
            sort8(SB); merge84(LB, SB);
        }
        __syncthreads();
    }
    #undef STAGE

    if (r0 < n){
        int base = r0*CTOT + (p*NSUB + g)*KSEL;
#pragma unroll
        for (int k = 0; k < KSEL; k++) g_ck[base+k] = LA[k];
    }
    if (r1 < n){
        int base = r1*CTOT + (p*NSUB + g)*KSEL;
#pragma unroll
        for (int k = 0; k < KSEL; k++) g_ck[base+k] = LB[k];
    }
}

// ---------------- refine stage A: approx-prune 30 keys -> 6, exact-refine only those ----------
template<int DIM>
__global__ void refineA_kernel(const float* __restrict__ X, const float* __restrict__ sq,
                               int n){
    const int Q4 = DIM/4;
    int t = blockIdx.x*blockDim.x + threadIdx.x;
    int i = t >> 3;
    int s = t & 7;
    if (i >= n) return;

    // 1) branchless approx top-6 over this thread's 30 keys (coalesced stream, no gather)
    float L[REFK];
#pragma unroll
    for (int k = 0; k < REFK; k++) L[k] = KEY_INIT;
    const float* kp = g_ck + (size_t)i*CTOT + s*CSLICE;
#pragma unroll 5
    for (int c = 0; c < CSLICE; c++) fbubble6(kp[c], L);

    // 2) exact fp32 distance for the 6 local winners only
    float4 xi[Q4];
#pragma unroll
    for (int q = 0; q < Q4; q++) xi[q] = reinterpret_cast<const float4*>(X)[i*Q4 + q];

    int ob = i*CMERGE + s*KNN;
#pragma unroll
    for (int k = 0; k < REFK; k++){
        u32 j = __float_as_uint(L[k]) & 0x7FFFu;
        float e = INFINITY;
        u32 jo = 0xFFFFFFFFu;
        if ((int)j < n && (int)j != i){
            float dot = 0.f;
#pragma unroll
            for (int q = 0; q < Q4; q++){
                float4 xj = reinterpret_cast<const float4*>(X)[j*Q4 + q];
                dot = fmaf(xi[q].x, xj.x, dot);
                dot = fmaf(xi[q].y, xj.y, dot);
                dot = fmaf(xi[q].z, xj.z, dot);
                dot = fmaf(xi[q].w, xj.w, dot);
            }
            e = fmaf(-2.f, dot, sq[j]);
            jo = j;
        }
        g_md[ob+k] = e;
        g_mi[ob+k] = (int)jo;
    }
}

// ---------------- dynamic edge conv (fused candidate merge; optional cat0 + transpose folds) ----
template<int F, bool CAT, bool TR>
__global__ void edgeconv_kernel(const float* __restrict__ X,
                                const float* __restrict__ W1, const float* __restrict__ b1,
                                const float* __restrict__ W2, const float* __restrict__ b2,
                                int n, float* __restrict__ Y, float* __restrict__ sqout,
                                float* __restrict__ tout){
    __shared__ float sW1[2*F*32];
    __shared__ float sb1[32];
    __shared__ float sW2[32*32];
    __shared__ float sb2[32];
    for (int t = threadIdx.x; t < 2*F*32; t += blockDim.x) sW1[t] = W1[t];
    for (int t = threadIdx.x; t < 32*32;  t += blockDim.x) sW2[t] = W2[t];
    if (threadIdx.x < 32){ sb1[threadIdx.x] = b1[threadIdx.x]; sb2[threadIdx.x] = b2[threadIdx.x]; }
    __syncthreads();
    int i = blockIdx.x*blockDim.x + threadIdx.x;
    if (i >= n) return;

    // fused refineB: merge 48 exact (dist, idx) candidates -> top-6
    float bd[KNN]; unsigned bi[KNN];
#pragma unroll
    for (int k = 0; k < KNN; k++){ bd[k] = INFINITY; bi[k] = 0xFFFFFFFFu; }
    int mbase = i*CMERGE;
    for (int c = 0; c < CMERGE; c++){
        float d = g_md[mbase+c];
        unsigned j = (unsigned)g_mi[mbase+c];
        if (j == 0xFFFFFFFFu) continue;
        if (d < bd[KNN-1] || (d == bd[KNN-1] && j < bi[KNN-1])){
            bd[KNN-1] = d; bi[KNN-1] = j;
#pragma unroll
            for (int k = KNN-1; k > 0; k--){
                bool sw = (bd[k] < bd[k-1]) || (bd[k] == bd[k-1] && bi[k] < bi[k-1]);
                if (sw){
                    float td = bd[k]; bd[k] = bd[k-1]; bd[k-1] = td;
                    unsigned ti = bi[k]; bi[k] = bi[k-1]; bi[k-1] = ti;
                }
            }
        }
    }

    float base[32];
#pragma unroll
    for (int c = 0; c < 32; c++) base[c] = sb1[c];
    for (int d = 0; d < F; d++){
        float v = X[i*F+d];
#pragma unroll
        for (int c = 0; c < 32; c++) base[c] = fmaf(v, sW1[d*32+c], base[c]);
    }
    float acc[32];
#pragma unroll
    for (int c = 0; c < 32; c++) acc[c] = -INFINITY;

    for (int kk = 0; kk < KNN; kk++){
        int j = (int)bi[kk];
        float h[32];
#pragma unroll
        for (int c = 0; c < 32; c++) h[c] = base[c];
        for (int d = 0; d < F; d++){
            float v = X[j*F+d] - X[i*F+d];
#pragma unroll
            for (int c = 0; c < 32; c++) h[c] = fmaf(v, sW1[(F+d)*32+c], h[c]);
        }
#pragma unroll
        for (int c = 0; c < 32; c++) h[c] = fmaxf(h[c], 0.f);
#pragma unroll
        for (int c = 0; c < 32; c++){
            float o = sb2[c];
#pragma unroll
            for (int k = 0; k < 32; k++) o = fmaf(h[k], sW2[k*32+c], o);
            acc[c] = fmaxf(acc[c], o);
        }
    }
    float sqv = 0.f;
#pragma unroll
    for (int c = 0; c < 32; c++){
        float r = fmaxf(acc[c], 0.f);
        Y[i*32+c] = r;
        if (CAT){ g_cat0[i*48+16+c] = r; g_agg2[i*48+16+c] = r; }
        if (TR) tout[i*32 + (c&3)*8 + (c>>2)] = r;
        sqv = fmaf(r, r, sqv);
    }
    if (sqout) sqout[i] = sqv;
}

__global__ void scatter2_kernel(const int* __restrict__ src, const int* __restrict__ dst, int E){
    int t = blockIdx.x*blockDim.x + threadIdx.x;
    int e = t / 12;
    if (e >= E) return;
    int q = t % 12;
    int s = src[e], d = dst[e];
    float4 v = reinterpret_cast<const float4*>(g_cat0)[s*12 + q];
    red4(&g_agg2[d*48 + q*4], v);
}

// ---------------- MLP layer 1 ----------------
__global__ void mlp1_kernel(const float* __restrict__ W, const float* __restrict__ b, int n){
    __shared__ float sW[96*96];
    __shared__ float sb[96];
    for (int t = threadIdx.x; t < 96*96; t += blockDim.x) sW[t] = W[t];
    for (int t = threadIdx.x; t < 96;    t += blockDim.x) sb[t] = b[t];
    __syncthreads();
    int i = blockIdx.x*blockDim.x + threadIdx.x;
    if (i >= n) return;
    float acc[96];
#pragma unroll
    for (int c = 0; c < 96; c++) acc[c] = sb[c];
    for (int d = 0; d < 64; d++){
        float v = g_x3[i*64+d];
#pragma unroll
        for (int c = 0; c < 96; c++) acc[c] = fmaf(v, sW[d*96+c], acc[c]);
    }
    for (int d = 0; d < 32; d++){
        float v = g_y2[i*32+d];
#pragma unroll
        for (int c = 0; c < 96; c++) acc[c] = fmaf(v, sW[(64+d)*96+c], acc[c]);
    }
#pragma unroll
    for (int c = 0; c < 96; c++) g_h1[i*96+c] = fmaxf(acc[c], 0.f);
}

// ---------------- MLP layers 2..out ----------------
__global__ void mlp2_kernel(const float* __restrict__ W2, const float* __restrict__ b2,
                            const float* __restrict__ W3, const float* __restrict__ b3,
                            const float* __restrict__ Wo, const float* __restrict__ bo,
                            int n, float* __restrict__ out){
    __shared__ float sW2[96*32]; __shared__ float sb2v[32];
    __shared__ float sW3[32*8];  __shared__ float sb3v[8];
    __shared__ float sWo[8];     __shared__ float sbo;
    for (int t = threadIdx.x; t < 96*32; t += blockDim.x) sW2[t] = W2[t];
    for (int t = threadIdx.x; t < 32*8;  t += blockDim.x) sW3[t] = W3[t];
    if (threadIdx.x < 32) sb2v[threadIdx.x] = b2[threadIdx.x];
    if (threadIdx.x < 8){ sb3v[threadIdx.x] = b3[threadIdx.x]; sWo[threadIdx.x] = Wo[threadIdx.x]; }
    if (threadIdx.x == 0) sbo = bo[0];
    __syncthreads();
    int i = blockIdx.x*blockDim.x + threadIdx.x;
    if (i >= n) return;
    float h[32];
#pragma unroll
    for (int c = 0; c < 32; c++) h[c] = sb2v[c];
    for (int d = 0; d < 96; d++){
        float v = g_h1[i*96+d];
#pragma unroll
        for (int c = 0; c < 32; c++) h[c] = fmaf(v, sW2[d*32+c], h[c]);
    }
#pragma unroll
    for (int c = 0; c < 32; c++) h[c] = fmaxf(h[c], 0.f);
    float g[8];
#pragma unroll
    for (int c = 0; c < 8; c++){
        float o = sb3v[c];
#pragma unroll
        for (int k = 0; k < 32; k++) o = fmaf(h[k], sW3[k*8+c], o);
        g[c] = fmaxf(o, 0.f);
    }
    float z = sbo;
#pragma unroll
    for (int c = 0; c < 8; c++) z = fmaf(g[c], sWo[c], z);
    out[i] = 1.0f / (1.0f + expf(-z));
}

// ---------------- launch ----------------
extern "C" void kernel_launch(void* const* d_in, const int* in_sizes, int n_in,
                              void* d_out, int out_size){
    const float* x   = (const float*)d_in[0];
    const int*   ei  = (const int*)  d_in[1];
    int n = in_sizes[0] / 16;
    int E = in_sizes[1] / 2;
    const int* src = ei;
    const int* dst = ei + E;

    const float* cW1 = (const float*)d_in[2];
    const float* cb1 = (const float*)d_in[5];
    const float* cW3 = (const float*)d_in[6];
    const float* cb3 = (const float*)d_in[9];
    const float* e1W1=(const float*)d_in[10]; const float* e1b1=(const float*)d_in[11];
    const float* e1W2=(const float*)d_in[12]; const float* e1b2=(const float*)d_in[13];
    const float* e2W1=(const float*)d_in[14]; const float* e2b1=(const float*)d_in[15];
    const float* e2W2=(const float*)d_in[16]; const float* e2b2=(const float*)d_in[17];
    const float* l1W =(const float*)d_in[18]; const float* l1b =(const float*)d_in[19];
    const float* l2W =(const float*)d_in[20]; const float* l2b =(const float*)d_in[21];
    const float* l3W =(const float*)d_in[22]; const float* l3b =(const float*)d_in[23];
    const float* oW  =(const float*)d_in[24]; const float* ob  =(const float*)d_in[25];
    float* out = (float*)d_out;

    void *p_agg1, *p_x1, *p_x1t, *p_sq1, *p_y1, *p_y1t, *p_sq2, *p_agg2, *p_x3, *p_y2;
    cudaGetSymbolAddress(&p_agg1, g_agg1);
    cudaGetSymbolAddress(&p_x1,   g_x1);
    cudaGetSymbolAddress(&p_x1t,  g_x1t);
    cudaGetSymbolAddress(&p_sq1,  g_sq1);
    cudaGetSymbolAddress(&p_y1,   g_y1);
    cudaGetSymbolAddress(&p_y1t,  g_y1t);
    cudaGetSymbolAddress(&p_sq2,  g_sq2);
    cudaGetSymbolAddress(&p_agg2, g_agg2);
    cudaGetSymbolAddress(&p_x3,   g_x3);
    cudaGetSymbolAddress(&p_y2,   g_y2);

    int nb = (n + 127) / 128;
    int tilesPerPart = (n + NPARTK*128 - 1) / (NPARTK*128);  // 11 for n=20000
    int chunk = tilesPerPart * 128;                          // 1408
    int npad = NPARTK * chunk;                               // 21120 <= NPAD
    dim3 knngrid(nb, NPARTK);
    int refA = (n*8 + 127) / 128;

    // FeaSt 1; x1 folded into cat0/agg2 AND transposed layout x1t
    init1_kernel<<<(n*16 + 255)/256, 256>>>(x, n, npad);
    scatter1_kernel<<<(E*4 + 255)/256, 256>>>(src, dst, x, E);
    feast_kernel<16,16,true,true,true><<<nb,128>>>((const float*)p_agg1, cW1, cb1, n,
                                                   (float*)p_x1, (float*)p_sq1, (float*)p_x1t);
    // kNN on x1: cp.async-pipelined tf32 MMA -> prune+exact refine (merge fused in edgeconv)
    knn_mma_kernel<16,16><<<knngrid,256>>>((const float*)p_x1t, (const float*)p_sq1, n, chunk);
    refineA_kernel<16><<<refA,128>>>((const float*)p_x1, (const float*)p_sq1, n);
    edgeconv_kernel<16,true,true><<<nb,128>>>((const float*)p_x1,
                                              e1W1, e1b1, e1W2, e1b2, n,
                                              (float*)p_y1, (float*)p_sq2, (float*)p_y1t);
    // FeaSt 2 on cat0 = [x1|y1]
    scatter2_kernel<<<(E*12 + 255)/256, 256>>>(src, dst, E);
    feast_kernel<48,64,false,false,false><<<nb,128>>>((const float*)p_agg2, cW3, cb3, n,
                                                      (float*)p_x3, nullptr, nullptr);
    // kNN on y1
    knn_mma_kernel<32,36><<<knngrid,256>>>((const float*)p_y1t, (const float*)p_sq2, n, chunk);
    refineA_kernel<32><<<refA,128>>>((const float*)p_y1, (const float*)p_sq2, n);
    edgeconv_kernel<32,false,false><<<nb,128>>>((const float*)p_y1,
                                                e2W1, e2b1, e2W2, e2b2, n,
                                                (float*)p_y2, nullptr, nullptr);
    // Final MLP
    mlp1_kernel<<<nb,128>>>(l1W, l1b, n);
    mlp2_kernel<<<nb,128>>>(l2W, l2b, l3W, l3b, oW, ob, n, out);
}

// round 17
// speedup vs baseline: 1.4387x; 1.0244x over previous
#include <cuda_runtime.h>
#include <math.h>

#define NMAX 20000
#define NPAD 21120                 /* NPARTK * chunk (15 * 11 * 128) */
#define KNN 6
#define KSEL 4                     /* per-bucket approx list depth */
#define REFK 6                     /* refine prune depth */
#define NPARTK 15
#define NSUB 4
#define CTOT (NPARTK*NSUB*KSEL)    /* 240 candidate keys per node */
#define CSLICE (CTOT/8)            /* 30 per refine thread */
#define CMERGE 48                  /* 8 slices x 6 */

typedef unsigned int u32;

// ---------------- scratch (device globals; no allocation allowed) ----------------
__device__ __align__(16) float g_cnt [NMAX];
__device__ __align__(16) float g_agg1[NMAX*16];
__device__ __align__(16) float g_x1  [NMAX*16];
__device__ __align__(16) float g_x1t [NPAD*16];   /* zero-init pad rows never written */
__device__ __align__(16) float g_sq1 [NPAD];
__device__ __align__(16) float g_y1  [NMAX*32];
__device__ __align__(16) float g_y1t [NPAD*32];
__device__ __align__(16) float g_sq2 [NPAD];
__device__ __align__(16) float g_cat0[NMAX*48];
__device__ __align__(16) float g_agg2[NMAX*48];
__device__ __align__(16) float g_x3  [NMAX*64];
__device__ __align__(16) float g_y2  [NMAX*32];
__device__ __align__(16) float g_h1  [NMAX*96];
__device__ __align__(16) float g_ck  [NMAX*CTOT];  /* packed approx keys */
__device__ __align__(16) float g_md  [NMAX*CMERGE];
__device__ __align__(16) int   g_mi  [NMAX*CMERGE];

#define MMA_TF32(c0,c1,c2,c3,a0,a1,a2,a3,b0,b1) \
    asm volatile("mma.sync.aligned.m16n8k8.row.col.f32.tf32.tf32.f32 " \
        "{%0,%1,%2,%3}, {%4,%5,%6,%7}, {%8,%9}, {%0,%1,%2,%3};" \
        : "+f"(c0), "+f"(c1), "+f"(c2), "+f"(c3) \
        : "r"(a0), "r"(a1), "r"(a2), "r"(a3), "r"(b0), "r"(b1))

// cp.async helpers (LDGSTS)
__device__ __forceinline__ void cpa16(u32 dst, const void* src){
    asm volatile("cp.async.cg.shared.global [%0], [%1], 16;" :: "r"(dst), "l"(src));
}
#define CPA_COMMIT() asm volatile("cp.async.commit_group;")
#define CPA_WAIT1()  asm volatile("cp.async.wait_group 1;")
#define CPA_WAIT0()  asm volatile("cp.async.wait_group 0;")

// vector reduction: 4 floats, one L2 transaction (sm_90+)
__device__ __forceinline__ void red4(float* a, float4 v){
    asm volatile("red.global.add.v4.f32 [%0], {%1, %2, %3, %4};"
        :: "l"(a), "f"(v.x), "f"(v.y), "f"(v.z), "f"(v.w) : "memory");
}

// float key: distance mantissa truncated to high 17 bits, j spliced into low 15.
__device__ __forceinline__ float fpack(float e, u32 j){
    return __uint_as_float((__float_as_uint(e) & 0xFFFF8000u) | j);
}
#define KEY_INIT __uint_as_float(0x7F7FFFFFu)

#define CMPX(a,b) { float _lo = fminf(a,b); b = fmaxf(a,b); a = _lo; }

// branchless sorted insert into ascending REFK-list (FMNMX only)
__device__ __forceinline__ void fbubble6(float key, float r[REFK]){
#pragma unroll
    for (int k = 0; k < REFK; k++){
        float lo = fminf(r[k], key);
        key      = fmaxf(r[k], key);
        r[k] = lo;
    }
}

// optimal 5-comparator sort of 4
__device__ __forceinline__ void sort4(float s[4]){
    CMPX(s[0],s[1]); CMPX(s[2],s[3]);
    CMPX(s[0],s[2]); CMPX(s[1],s[3]);
    CMPX(s[1],s[2]);
}

// a <- lowest-4 (sorted) of two ascending sorted-4 lists (bitonic halver + M4)
__device__ __forceinline__ void low4(float a[4], const float b[4]){
    float t0 = fminf(a[0], b[3]);
    float t1 = fminf(a[1], b[2]);
    float t2 = fminf(a[2], b[1]);
    float t3 = fminf(a[3], b[0]);
    CMPX(t0,t2); CMPX(t1,t3);
    CMPX(t0,t1); CMPX(t2,t3);
    a[0]=t0; a[1]=t1; a[2]=t2; a[3]=t3;
}

// ---------------- init: agg1 = x (self loop), cnt = 1, sq pads = 1e30 ----------------
__global__ void init1_kernel(const float* __restrict__ x, int n, int npad){
    int t = blockIdx.x*blockDim.x + threadIdx.x;
    if (t < n*16) g_agg1[t] = x[t];
    if (t < n)    g_cnt[t]  = 1.0f;
    if (t >= n && t < npad){ g_sq1[t] = 1e30f; g_sq2[t] = 1e30f; }
}

// ---------------- scatter-add of x[src] into agg1[dst] (v4 red), count edges ----------------
__global__ void scatter1_kernel(const int* __restrict__ src, const int* __restrict__ dst,
                                const float* __restrict__ x, int E){
    int t = blockIdx.x*blockDim.x + threadIdx.x;
    int e = t >> 2;
    if (e >= E) return;
    int q = t & 3;
    int s = src[e], d = dst[e];
    if (q == 0) atomicAdd(&g_cnt[d], 1.0f);
    float4 v = reinterpret_cast<const float4*>(x)[s*4 + q];
    red4(&g_agg1[d*16 + q*4], v);
}

// ---------------- feast: out = relu((agg/cnt) @ W + b); optional sq/cat0/transpose folds --------
template<int IN, int OUT, bool WSQ, bool CAT, bool TR>
__global__ void feast_kernel(const float* __restrict__ agg, const float* __restrict__ W,
                             const float* __restrict__ b, int n,
                             float* __restrict__ out, float* __restrict__ sqout,
                             float* __restrict__ tout){
    __shared__ float sW[IN*OUT];
    __shared__ float sb[OUT];
    for (int t = threadIdx.x; t < IN*OUT; t += blockDim.x) sW[t] = W[t];
    for (int t = threadIdx.x; t < OUT;    t += blockDim.x) sb[t] = b[t];
    __syncthreads();
    int i = blockIdx.x*blockDim.x + threadIdx.x;
    if (i >= n) return;
    float inv = 1.0f / g_cnt[i];
    float acc[OUT];
#pragma unroll
    for (int c = 0; c < OUT; c++) acc[c] = sb[c];
    for (int d = 0; d < IN; d++){
        float v = agg[i*IN+d] * inv;
#pragma unroll
        for (int c = 0; c < OUT; c++) acc[c] = fmaf(v, sW[d*OUT+c], acc[c]);
    }
    float sq = 0.f;
#pragma unroll
    for (int c = 0; c < OUT; c++){
        float r = fmaxf(acc[c], 0.f);
        out[i*OUT+c] = r;
        if (CAT){ g_cat0[i*48+c] = r; g_agg2[i*48+c] = r; }
        if (TR) tout[i*OUT + (c&3)*(OUT/4) + (c>>2)] = r;
        sq = fmaf(r, r, sq);
    }
    if (WSQ) sqout[i] = sq;
}

// ---------------- tensor-core kNN: cp.async double-buffered, tf32 MMA, sorted selection --------
template<int DIM, int PAD>
__global__ void __launch_bounds__(256,4)
knn_mma_kernel(const float* __restrict__ Xt, const float* __restrict__ sq,
               int n, int chunk){
    const int KC = DIM/8;
    const int Q4 = DIM/4;
    __shared__ float bs[2][128*PAD];
    __shared__ float sqs[2][128];

    int tid = threadIdx.x;
    int w = tid >> 5;
    int lane = tid & 31;
    int g = lane & 3;
    int rsub = lane >> 2;
    int qbase = blockIdx.x*128 + w*16;
    int r0 = qbase + rsub;
    int r1 = r0 + 8;
    int p = blockIdx.y;
    int jbeg = p * chunk;
    int T = chunk >> 7;

    int rr0 = min(r0, n-1), rr1 = min(r1, n-1);
    u32 a0[KC], a1[KC], a2[KC], a3[KC];
    {
        const float2* xa = (const float2*)(Xt + (size_t)rr0*DIM) + g*(Q4/2);
        const float2* xb = (const float2*)(Xt + (size_t)rr1*DIM) + g*(Q4/2);
#pragma unroll
        for (int kc = 0; kc < KC; kc++){
            float2 va = xa[kc], vb = xb[kc];
            a0[kc] = __float_as_uint(-2.0f * va.x);
            a2[kc] = __float_as_uint(-2.0f * va.y);
            a1[kc] = __float_as_uint(-2.0f * vb.x);
            a3[kc] = __float_as_uint(-2.0f * vb.y);
        }
    }

    u32 sb0 = (u32)__cvta_generic_to_shared(&bs[0][0]);
    u32 sb1 = (u32)__cvta_generic_to_shared(&bs[1][0]);
    u32 sq0 = (u32)__cvta_generic_to_shared(&sqs[0][0]);
    u32 sq1 = (u32)__cvta_generic_to_shared(&sqs[1][0]);

    float LA[KSEL], LB[KSEL];
#pragma unroll
    for (int k = 0; k < KSEL; k++){ LA[k] = KEY_INIT; LB[k] = KEY_INIT; }

    #define STAGE(BUF, JT) { \
        u32 _bb = (BUF) ? sb1 : sb0; \
        u32 _bq = (BUF) ? sq1 : sq0; \
        _Pragma("unroll") \
        for (int idx = tid; idx < 128*Q4; idx += 256){ \
            int jr = idx / Q4, q = idx - jr*Q4; \
            cpa16(_bb + (u32)(jr*PAD + q*4)*4u, Xt + (size_t)((JT)+jr)*DIM + q*4); \
        } \
        if (tid < 32) cpa16(_bq + tid*16u, sq + (JT) + tid*4); \
    }

    STAGE(0, jbeg);
    CPA_COMMIT();

    for (int t = 0; t < T; t++){
        int cur = t & 1;
        if (t + 1 < T){
            STAGE(1-cur, jbeg + (t+1)*128);
            CPA_COMMIT();
            CPA_WAIT1();
        } else {
            CPA_WAIT0();
        }
        __syncthreads();

        const float* bsc = &bs[cur][0];
        const float* sqc = &sqs[cur][0];
        int jt = jbeg + t*128;

#pragma unroll
        for (int jg = 0; jg < 128; jg += 32){
            float SA[8], SB[8];
#pragma unroll
            for (int st = 0; st < 4; st++){
                int js = jg + st*8;
                float2 s2 = *reinterpret_cast<const float2*>(&sqc[js + 2*g]);
                float c0 = s2.x, c1 = s2.y, c2 = s2.x, c3 = s2.y;
                const float* row = &bsc[(js + rsub)*PAD + g*Q4];
                if (DIM == 16){
                    float4 bf = *reinterpret_cast<const float4*>(row);
                    MMA_TF32(c0,c1,c2,c3, a0[0],a1[0],a2[0],a3[0],
                             __float_as_uint(bf.x), __float_as_uint(bf.y));
                    MMA_TF32(c0,c1,c2,c3, a0[KC-1],a1[KC-1],a2[KC-1],a3[KC-1],
                             __float_as_uint(bf.z), __float_as_uint(bf.w));
                } else {
                    float4 b1f = *reinterpret_cast<const float4*>(row);
                    float4 b2f = *reinterpret_cast<const float4*>(row + 4);
                    MMA_TF32(c0,c1,c2,c3, a0[0],a1[0],a2[0],a3[0],
                             __float_as_uint(b1f.x), __float_as_uint(b1f.y));
                    MMA_TF32(c0,c1,c2,c3, a0[1],a1[1],a2[1],a3[1],
                             __float_as_uint(b1f.z), __float_as_uint(b1f.w));
                    MMA_TF32(c0,c1,c2,c3, a0[KC-2],a1[KC-2],a2[KC-2],a3[KC-2],
                             __float_as_uint(b2f.x), __float_as_uint(b2f.y));
                    MMA_TF32(c0,c1,c2,c3, a0[KC-1],a1[KC-1],a2[KC-1],a3[KC-1],
                             __float_as_uint(b2f.z), __float_as_uint(b2f.w));
                }
                u32 j0 = (u32)(jt + js + 2*g);
                SA[st*2+0] = fpack(c0, j0);
                SA[st*2+1] = fpack(c1, j0+1);
                SB[st*2+0] = fpack(c2, j0);
                SB[st*2+1] = fpack(c3, j0+1);
            }
            // exact lowest-4-sorted of each batch-8, then exact merge into L
            sort4(&SA[0]); sort4(&SA[4]); low4(&SA[0], &SA[4]); low4(LA, &SA[0]);
            sort4(&SB[0]); sort4(&SB[4]); low4(&SB[0], &SB[4]); low4(LB, &SB[0]);
        }
        __syncthreads();
    }
    #undef STAGE

    if (r0 < n){
        int base = r0*CTOT + (p*NSUB + g)*KSEL;
#pragma unroll
        for (int k = 0; k < KSEL; k++) g_ck[base+k] = LA[k];
    }
    if (r1 < n){
        int base = r1*CTOT + (p*NSUB + g)*KSEL;
#pragma unroll
        for (int k = 0; k < KSEL; k++) g_ck[base+k] = LB[k];
    }
}

// ---------------- refine stage A: approx-prune 30 keys -> 6, exact-refine only those ----------
template<int DIM>
__global__ void refineA_kernel(const float* __restrict__ X, const float* __restrict__ sq,
                               int n){
    const int Q4 = DIM/4;
    int t = blockIdx.x*blockDim.x + threadIdx.x;
    int i = t >> 3;
    int s = t & 7;
    if (i >= n) return;

    float L[REFK];
#pragma unroll
    for (int k = 0; k < REFK; k++) L[k] = KEY_INIT;
    const float* kp = g_ck + (size_t)i*CTOT + s*CSLICE;
#pragma unroll 5
    for (int c = 0; c < CSLICE; c++) fbubble6(kp[c], L);

    float4 xi[Q4];
#pragma unroll
    for (int q = 0; q < Q4; q++) xi[q] = reinterpret_cast<const float4*>(X)[i*Q4 + q];

    int ob = i*CMERGE + s*KNN;
#pragma unroll
    for (int k = 0; k < REFK; k++){
        u32 j = __float_as_uint(L[k]) & 0x7FFFu;
        float e = INFINITY;
        u32 jo = 0xFFFFFFFFu;
        if ((int)j < n && (int)j != i){
            float dot = 0.f;
#pragma unroll
            for (int q = 0; q < Q4; q++){
                float4 xj = reinterpret_cast<const float4*>(X)[j*Q4 + q];
                dot = fmaf(xi[q].x, xj.x, dot);
                dot = fmaf(xi[q].y, xj.y, dot);
                dot = fmaf(xi[q].z, xj.z, dot);
                dot = fmaf(xi[q].w, xj.w, dot);
            }
            e = fmaf(-2.f, dot, sq[j]);
            jo = j;
        }
        g_md[ob+k] = e;
        g_mi[ob+k] = (int)jo;
    }
}

// ---------------- dynamic edge conv (fused candidate merge; optional cat0 + transpose folds) ----
template<int F, bool CAT, bool TR>
__global__ void edgeconv_kernel(const float* __restrict__ X,
                                const float* __restrict__ W1, const float* __restrict__ b1,
                                const float* __restrict__ W2, const float* __restrict__ b2,
                                int n, float* __restrict__ Y, float* __restrict__ sqout,
                                float* __restrict__ tout){
    __shared__ float sW1[2*F*32];
    __shared__ float sb1[32];
    __shared__ float sW2[32*32];
    __shared__ float sb2[32];
    for (int t = threadIdx.x; t < 2*F*32; t += blockDim.x) sW1[t] = W1[t];
    for (int t = threadIdx.x; t < 32*32;  t += blockDim.x) sW2[t] = W2[t];
    if (threadIdx.x < 32){ sb1[threadIdx.x] = b1[threadIdx.x]; sb2[threadIdx.x] = b2[threadIdx.x]; }
    __syncthreads();
    int i = blockIdx.x*blockDim.x + threadIdx.x;
    if (i >= n) return;

    // fused refineB: merge 48 exact (dist, idx) candidates -> top-6
    float bd[KNN]; unsigned bi[KNN];
#pragma unroll
    for (int k = 0; k < KNN; k++){ bd[k] = INFINITY; bi[k] = 0xFFFFFFFFu; }
    int mbase = i*CMERGE;
    for (int c = 0; c < CMERGE; c++){
        float d = g_md[mbase+c];
        unsigned j = (unsigned)g_mi[mbase+c];
        if (j == 0xFFFFFFFFu) continue;
        if (d < bd[KNN-1] || (d == bd[KNN-1] && j < bi[KNN-1])){
            bd[KNN-1] = d; bi[KNN-1] = j;
#pragma unroll
            for (int k = KNN-1; k > 0; k--){
                bool sw = (bd[k] < bd[k-1]) || (bd[k] == bd[k-1] && bi[k] < bi[k-1]);
                if (sw){
                    float td = bd[k]; bd[k] = bd[k-1]; bd[k-1] = td;
                    unsigned ti = bi[k]; bi[k] = bi[k-1]; bi[k-1] = ti;
                }
            }
        }
    }

    float base[32];
#pragma unroll
    for (int c = 0; c < 32; c++) base[c] = sb1[c];
    for (int d = 0; d < F; d++){
        float v = X[i*F+d];
#pragma unroll
        for (int c = 0; c < 32; c++) base[c] = fmaf(v, sW1[d*32+c], base[c]);
    }
    float acc[32];
#pragma unroll
    for (int c = 0; c < 32; c++) acc[c] = -INFINITY;

    for (int kk = 0; kk < KNN; kk++){
        int j = (int)bi[kk];
        float h[32];
#pragma unroll
        for (int c = 0; c < 32; c++) h[c] = base[c];
        for (int d = 0; d < F; d++){
            float v = X[j*F+d] - X[i*F+d];
#pragma unroll
            for (int c = 0; c < 32; c++) h[c] = fmaf(v, sW1[(F+d)*32+c], h[c]);
        }
#pragma unroll
        for (int c = 0; c < 32; c++) h[c] = fmaxf(h[c], 0.f);
#pragma unroll
        for (int c = 0; c < 32; c++){
            float o = sb2[c];
#pragma unroll
            for (int k = 0; k < 32; k++) o = fmaf(h[k], sW2[k*32+c], o);
            acc[c] = fmaxf(acc[c], o);
        }
    }
    float sqv = 0.f;
#pragma unroll
    for (int c = 0; c < 32; c++){
        float r = fmaxf(acc[c], 0.f);
        Y[i*32+c] = r;
        if (CAT){ g_cat0[i*48+16+c] = r; g_agg2[i*48+16+c] = r; }
        if (TR) tout[i*32 + (c&3)*8 + (c>>2)] = r;
        sqv = fmaf(r, r, sqv);
    }
    if (sqout) sqout[i] = sqv;
}

__global__ void scatter2_kernel(const int* __restrict__ src, const int* __restrict__ dst, int E){
    int t = blockIdx.x*blockDim.x + threadIdx.x;
    int e = t / 12;
    if (e >= E) return;
    int q = t % 12;
    int s = src[e], d = dst[e];
    float4 v = reinterpret_cast<const float4*>(g_cat0)[s*12 + q];
    red4(&g_agg2[d*48 + q*4], v);
}

// ---------------- MLP layer 1 ----------------
__global__ void mlp1_kernel(const float* __restrict__ W, const float* __restrict__ b, int n){
    __shared__ float sW[96*96];
    __shared__ float sb[96];
    for (int t = threadIdx.x; t < 96*96; t += blockDim.x) sW[t] = W[t];
    for (int t = threadIdx.x; t < 96;    t += blockDim.x) sb[t] = b[t];
    __syncthreads();
    int i = blockIdx.x*blockDim.x + threadIdx.x;
    if (i >= n) return;
    float acc[96];
#pragma unroll
    for (int c = 0; c < 96; c++) acc[c] = sb[c];
    for (int d = 0; d < 64; d++){
        float v = g_x3[i*64+d];
#pragma unroll
        for (int c = 0; c < 96; c++) acc[c] = fmaf(v, sW[d*96+c], acc[c]);
    }
    for (int d = 0; d < 32; d++){
        float v = g_y2[i*32+d];
#pragma unroll
        for (int c = 0; c < 96; c++) acc[c] = fmaf(v, sW[(64+d)*96+c], acc[c]);
    }
#pragma unroll
    for (int c = 0; c < 96; c++) g_h1[i*96+c] = fmaxf(acc[c], 0.f);
}

// ---------------- MLP layers 2..out ----------------
__global__ void mlp2_kernel(const float* __restrict__ W2, const float* __restrict__ b2,
                            const float* __restrict__ W3, const float* __restrict__ b3,
                            const float* __restrict__ Wo, const float* __restrict__ bo,
                            int n, float* __restrict__ out){
    __shared__ float sW2[96*32]; __shared__ float sb2v[32];
    __shared__ float sW3[32*8];  __shared__ float sb3v[8];
    __shared__ float sWo[8];     __shared__ float sbo;
    for (int t = threadIdx.x; t < 96*32; t += blockDim.x) sW2[t] = W2[t];
    for (int t = threadIdx.x; t < 32*8;  t += blockDim.x) sW3[t] = W3[t];
    if (threadIdx.x < 32) sb2v[threadIdx.x] = b2[threadIdx.x];
    if (threadIdx.x < 8){ sb3v[threadIdx.x] = b3[threadIdx.x]; sWo[threadIdx.x] = Wo[threadIdx.x]; }
    if (threadIdx.x == 0) sbo = bo[0];
    __syncthreads();
    int i = blockIdx.x*blockDim.x + threadIdx.x;
    if (i >= n) return;
    float h[32];
#pragma unroll
    for (int c = 0; c < 32; c++) h[c] = sb2v[c];
    for (int d = 0; d < 96; d++){
        float v = g_h1[i*96+d];
#pragma unroll
        for (int c = 0; c < 32; c++) h[c] = fmaf(v, sW2[d*32+c], h[c]);
    }
#pragma unroll
    for (int c = 0; c < 32; c++) h[c] = fmaxf(h[c], 0.f);
    float g[8];
#pragma unroll
    for (int c = 0; c < 8; c++){
        float o = sb3v[c];
#pragma unroll
        for (int k = 0; k < 32; k++) o = fmaf(h[k], sW3[k*8+c], o);
        g[c] = fmaxf(o, 0.f);
    }
    float z = sbo;
#pragma unroll
    for (int c = 0; c < 8; c++) z = fmaf(g[c], sWo[c], z);
    out[i] = 1.0f / (1.0f + expf(-z));
}

// ---------------- launch ----------------
extern "C" void kernel_launch(void* const* d_in, const int* in_sizes, int n_in,
                              void* d_out, int out_size){
    const float* x   = (const float*)d_in[0];
    const int*   ei  = (const int*)  d_in[1];
    int n = in_sizes[0] / 16;
    int E = in_sizes[1] / 2;
    const int* src = ei;
    const int* dst = ei + E;

    const float* cW1 = (const float*)d_in[2];
    const float* cb1 = (const float*)d_in[5];
    const float* cW3 = (const float*)d_in[6];
    const float* cb3 = (const float*)d_in[9];
    const float* e1W1=(const float*)d_in[10]; const float* e1b1=(const float*)d_in[11];
    const float* e1W2=(const float*)d_in[12]; const float* e1b2=(const float*)d_in[13];
    const float* e2W1=(const float*)d_in[14]; const float* e2b1=(const float*)d_in[15];
    const float* e2W2=(const float*)d_in[16]; const float* e2b2=(const float*)d_in[17];
    const float* l1W =(const float*)d_in[18]; const float* l1b =(const float*)d_in[19];
    const float* l2W =(const float*)d_in[20]; const float* l2b =(const float*)d_in[21];
    const float* l3W =(const float*)d_in[22]; const float* l3b =(const float*)d_in[23];
    const float* oW  =(const float*)d_in[24]; const float* ob  =(const float*)d_in[25];
    float* out = (float*)d_out;

    void *p_agg1, *p_x1, *p_x1t, *p_sq1, *p_y1, *p_y1t, *p_sq2, *p_agg2, *p_x3, *p_y2;
    cudaGetSymbolAddress(&p_agg1, g_agg1);
    cudaGetSymbolAddress(&p_x1,   g_x1);
    cudaGetSymbolAddress(&p_x1t,  g_x1t);
    cudaGetSymbolAddress(&p_sq1,  g_sq1);
    cudaGetSymbolAddress(&p_y1,   g_y1);
    cudaGetSymbolAddress(&p_y1t,  g_y1t);
    cudaGetSymbolAddress(&p_sq2,  g_sq2);
    cudaGetSymbolAddress(&p_agg2, g_agg2);
    cudaGetSymbolAddress(&p_x3,   g_x3);
    cudaGetSymbolAddress(&p_y2,   g_y2);

    // one-time side stream + fork/join events (created on first, non-captured call;
    // every call performs the identical captured launch/event sequence)
    static cudaStream_t s2 = nullptr;
    static cudaEvent_t evF = nullptr, evJ = nullptr;
    if (s2 == nullptr){
        cudaStreamCreateWithFlags(&s2, cudaStreamNonBlocking);
        cudaEventCreateWithFlags(&evF, cudaEventDisableTiming);
        cudaEventCreateWithFlags(&evJ, cudaEventDisableTiming);
    }

    int nb = (n + 127) / 128;
    int tilesPerPart = (n + NPARTK*128 - 1) / (NPARTK*128);  // 11 for n=20000
    int chunk = tilesPerPart * 128;                          // 1408
    int npad = NPARTK * chunk;                               // 21120 <= NPAD
    dim3 knngrid(nb, NPARTK);
    int refA = (n*8 + 127) / 128;

    // FeaSt 1; x1 folded into cat0/agg2 AND transposed layout x1t
    init1_kernel<<<(n*16 + 255)/256, 256>>>(x, n, npad);
    scatter1_kernel<<<(E*4 + 255)/256, 256>>>(src, dst, x, E);
    feast_kernel<16,16,true,true,true><<<nb,128>>>((const float*)p_agg1, cW1, cb1, n,
                                                   (float*)p_x1, (float*)p_sq1, (float*)p_x1t);
    // kNN on x1
    knn_mma_kernel<16,16><<<knngrid,256>>>((const float*)p_x1t, (const float*)p_sq1, n, chunk);
    refineA_kernel<16><<<refA,128>>>((const float*)p_x1, (const float*)p_sq1, n);
    edgeconv_kernel<16,true,true><<<nb,128>>>((const float*)p_x1,
                                              e1W1, e1b1, e1W2, e1b2, n,
                                              (float*)p_y1, (float*)p_sq2, (float*)p_y1t);

    // fork: {scatter2 -> feast2} on s2 runs concurrently with {knn32 -> refineA32 -> edgeconv2}
    cudaEventRecord(evF, 0);
    cudaStreamWaitEvent(s2, evF, 0);
    scatter2_kernel<<<(E*12 + 255)/256, 256, 0, s2>>>(src, dst, E);
    feast_kernel<48,64,false,false,false><<<nb,128,0,s2>>>((const float*)p_agg2, cW3, cb3, n,
                                                           (float*)p_x3, nullptr, nullptr);
    cudaEventRecord(evJ, s2);

    knn_mma_kernel<32,36><<<knngrid,256>>>((const float*)p_y1t, (const float*)p_sq2, n, chunk);
    refineA_kernel<32><<<refA,128>>>((const float*)p_y1, (const float*)p_sq2, n);
    edgeconv_kernel<32,false,false><<<nb,128>>>((const float*)p_y1,
                                                e2W1, e2b1, e2W2, e2b2, n,
                                                (float*)p_y2, nullptr, nullptr);
    // join
    cudaStreamWaitEvent(0, evJ, 0);

    // Final MLP
    mlp1_kernel<<<nb,128>>>(l1W, l1b, n);
    mlp2_kernel<<<nb,128>>>(l2W, l2b, l3W, l3b, oW, ob, n, out);
}